// round 1
// baseline (speedup 1.0000x reference)
#include <cuda_runtime.h>
#include <cuda_bf16.h>
#include <math.h>

// Problem constants
#define BATCH 4
#define SEQ   2048
#define DMODEL 1024
#define BS    (BATCH * SEQ)          // 8192

// ---------------------------------------------------------------------------
// Scratch (allocation-free: __device__ globals)
// ---------------------------------------------------------------------------
__device__ float g_x[BS * DMODEL];          // gelu(tokens)
__device__ float g_q[BS * DMODEL];
__device__ float g_k[BS * DMODEL];
__device__ float g_v[BS * DMODEL];
__device__ float g_s[BATCH * SEQ * SEQ];    // scores / attn  (64 MB)
__device__ float g_m[BS * DMODEL];          // mixed

// ---------------------------------------------------------------------------
// GELU (exact erf form)
// ---------------------------------------------------------------------------
__global__ void gelu_kernel(const float* __restrict__ in, float* __restrict__ out, int n) {
    int i = blockIdx.x * blockDim.x + threadIdx.x;
    if (i < n) {
        float t = in[i];
        out[i] = 0.5f * t * (1.0f + erff(t * 0.70710678118654752f));
    }
}

// ---------------------------------------------------------------------------
// Batched GEMM: C = alpha * A @ op(B) [+ bias] [+ resid]
//   A: [M,K] row-major (per batch, stride sA)
//   B: TRANSB ? [N,K] : [K,N] row-major (stride sB)
//   C: [M,N] row-major (stride sC); resid same layout as C
// Block tile 128x128, K-tile 8, 256 threads, 8x8 per-thread micro-tile.
// All dims assumed divisible by tiles (true for this problem).
// ---------------------------------------------------------------------------
#define BM 128
#define BN 128
#define BKK 8

template<bool TRANSB, bool BIAS, bool RESID>
__global__ __launch_bounds__(256)
void gemm_kernel(const float* __restrict__ A, const float* __restrict__ B,
                 const float* __restrict__ bias, const float* __restrict__ resid,
                 float* __restrict__ C, int M, int N, int K, float alpha,
                 long long sA, long long sB, long long sC)
{
    __shared__ float As[BKK][BM];
    __shared__ float Bsm[BKK][BN];

    const int tid = threadIdx.x;
    const float* Ab = A + (long long)blockIdx.z * sA;
    const float* Bb = B + (long long)blockIdx.z * sB;
    float*       Cb = C + (long long)blockIdx.z * sC;
    const float* Rb = RESID ? (resid + (long long)blockIdx.z * sC) : nullptr;

    const int m0 = blockIdx.y * BM;
    const int n0 = blockIdx.x * BN;

    // A tile loader: 128 rows x 8 cols = 256 float4
    const int arow = tid >> 1;
    const int aseg = (tid & 1) * 4;

    // B tile loader
    int brow, bseg;
    if (TRANSB) { brow = tid >> 1;  bseg = (tid & 1)  * 4; }   // [N,K] rows
    else        { brow = tid >> 5;  bseg = (tid & 31) * 4; }   // [K,N] rows

    const int ty = tid >> 4, tx = tid & 15;
    const int rowb = ty * 8, colb = tx * 8;

    float acc[8][8];
    #pragma unroll
    for (int i = 0; i < 8; i++)
        #pragma unroll
        for (int j = 0; j < 8; j++) acc[i][j] = 0.0f;

    for (int k0 = 0; k0 < K; k0 += BKK) {
        // load A (transpose into As[k][m])
        {
            float4 av = *(const float4*)&Ab[(long long)(m0 + arow) * K + k0 + aseg];
            As[aseg + 0][arow] = av.x;
            As[aseg + 1][arow] = av.y;
            As[aseg + 2][arow] = av.z;
            As[aseg + 3][arow] = av.w;
        }
        // load B into Bs[k][n]
        if (TRANSB) {
            float4 bv = *(const float4*)&Bb[(long long)(n0 + brow) * K + k0 + bseg];
            Bsm[bseg + 0][brow] = bv.x;
            Bsm[bseg + 1][brow] = bv.y;
            Bsm[bseg + 2][brow] = bv.z;
            Bsm[bseg + 3][brow] = bv.w;
        } else {
            float4 bv = *(const float4*)&Bb[(long long)(k0 + brow) * N + n0 + bseg];
            *(float4*)&Bsm[brow][bseg] = bv;
        }
        __syncthreads();

        #pragma unroll
        for (int kk = 0; kk < BKK; kk++) {
            float a[8], b[8];
            #pragma unroll
            for (int i = 0; i < 8; i++) a[i] = As[kk][rowb + i];
            #pragma unroll
            for (int j = 0; j < 8; j++) b[j] = Bsm[kk][colb + j];
            #pragma unroll
            for (int i = 0; i < 8; i++)
                #pragma unroll
                for (int j = 0; j < 8; j++)
                    acc[i][j] = fmaf(a[i], b[j], acc[i][j]);
        }
        __syncthreads();
    }

    // epilogue
    #pragma unroll
    for (int i = 0; i < 8; i++) {
        const long long mrow = (long long)(m0 + rowb + i) * N;
        #pragma unroll
        for (int j = 0; j < 8; j += 4) {
            const int n = n0 + colb + j;
            float4 v;
            v.x = alpha * acc[i][j + 0];
            v.y = alpha * acc[i][j + 1];
            v.z = alpha * acc[i][j + 2];
            v.w = alpha * acc[i][j + 3];
            if (BIAS) {
                v.x += bias[n + 0]; v.y += bias[n + 1];
                v.z += bias[n + 2]; v.w += bias[n + 3];
            }
            if (RESID) {
                float4 r = *(const float4*)&Rb[mrow + n];
                v.x += r.x; v.y += r.y; v.z += r.z; v.w += r.w;
            }
            *(float4*)&Cb[mrow + n] = v;
        }
    }
}

// ---------------------------------------------------------------------------
// Row softmax (in place). One block per row, 256 threads, cols = SEQ.
// ---------------------------------------------------------------------------
__global__ __launch_bounds__(256)
void softmax_kernel(float* __restrict__ S, int cols)
{
    float* p = S + (long long)blockIdx.x * cols;
    const int tid = threadIdx.x;
    __shared__ float red[8];

    // 1) row max
    float mx = -INFINITY;
    for (int c = tid; c < cols; c += 256) mx = fmaxf(mx, p[c]);
    #pragma unroll
    for (int o = 16; o > 0; o >>= 1) mx = fmaxf(mx, __shfl_xor_sync(0xffffffffu, mx, o));
    if ((tid & 31) == 0) red[tid >> 5] = mx;
    __syncthreads();
    float rmax = red[0];
    #pragma unroll
    for (int i = 1; i < 8; i++) rmax = fmaxf(rmax, red[i]);
    __syncthreads();

    // 2) exp + sum
    float sum = 0.0f;
    for (int c = tid; c < cols; c += 256) {
        float e = __expf(p[c] - rmax);
        p[c] = e;
        sum += e;
    }
    #pragma unroll
    for (int o = 16; o > 0; o >>= 1) sum += __shfl_xor_sync(0xffffffffu, sum, o);
    if ((tid & 31) == 0) red[tid >> 5] = sum;
    __syncthreads();
    float rsum = 0.0f;
    #pragma unroll
    for (int i = 0; i < 8; i++) rsum += red[i];
    const float inv = 1.0f / rsum;

    // 3) normalize
    for (int c = tid; c < cols; c += 256) p[c] *= inv;
}

// ---------------------------------------------------------------------------
// Launch
// ---------------------------------------------------------------------------
extern "C" void kernel_launch(void* const* d_in, const int* in_sizes, int n_in,
                              void* d_out, int out_size)
{
    const float* tokens = (const float*)d_in[0];
    const float* Wq = (const float*)d_in[1];
    const float* bq = (const float*)d_in[2];
    const float* Wk = (const float*)d_in[3];
    const float* bk = (const float*)d_in[4];
    const float* Wv = (const float*)d_in[5];
    const float* bv = (const float*)d_in[6];
    const float* Wo = (const float*)d_in[7];
    const float* bo = (const float*)d_in[8];
    float* out = (float*)d_out;

    float *x, *q, *k, *v, *s, *m;
    cudaGetSymbolAddress((void**)&x, g_x);
    cudaGetSymbolAddress((void**)&q, g_q);
    cudaGetSymbolAddress((void**)&k, g_k);
    cudaGetSymbolAddress((void**)&v, g_v);
    cudaGetSymbolAddress((void**)&s, g_s);
    cudaGetSymbolAddress((void**)&m, g_m);

    const int nTok = BS * DMODEL;
    const float scale = 1.0f / 32.0f;   // 1/sqrt(1024)

    // 1) gelu
    gelu_kernel<<<(nTok + 255) / 256, 256>>>(tokens, x, nTok);

    // 2) q, k, v projections: [8192,1024] @ [1024,1024] + bias
    {
        dim3 grid(DMODEL / BN, BS / BM, 1);
        gemm_kernel<false, true, false><<<grid, 256>>>(x, Wq, bq, nullptr, q,
            BS, DMODEL, DMODEL, 1.0f, 0, 0, 0);
        gemm_kernel<false, true, false><<<grid, 256>>>(x, Wk, bk, nullptr, k,
            BS, DMODEL, DMODEL, 1.0f, 0, 0, 0);
        gemm_kernel<false, true, false><<<grid, 256>>>(x, Wv, bv, nullptr, v,
            BS, DMODEL, DMODEL, 1.0f, 0, 0, 0);
    }

    // 3) scores = scale * Q @ K^T, batched
    {
        dim3 grid(SEQ / BN, SEQ / BM, BATCH);
        gemm_kernel<true, false, false><<<grid, 256>>>(q, k, nullptr, nullptr, s,
            SEQ, SEQ, DMODEL, scale,
            (long long)SEQ * DMODEL, (long long)SEQ * DMODEL, (long long)SEQ * SEQ);
    }

    // 4) softmax over rows (8192 rows of 2048)
    softmax_kernel<<<BS, 256>>>(s, SEQ);

    // 5) mixed = attn @ V, batched
    {
        dim3 grid(DMODEL / BN, SEQ / BM, BATCH);
        gemm_kernel<false, false, false><<<grid, 256>>>(s, v, nullptr, nullptr, m,
            SEQ, DMODEL, SEQ, 1.0f,
            (long long)SEQ * SEQ, (long long)SEQ * DMODEL, (long long)SEQ * DMODEL);
    }

    // 6) out = mixed @ Wo + bo + tokens
    {
        dim3 grid(DMODEL / BN, BS / BM, 1);
        gemm_kernel<false, true, true><<<grid, 256>>>(m, Wo, bo, tokens, out,
            BS, DMODEL, DMODEL, 1.0f, 0, 0, 0);
    }
}

// round 3
// speedup vs baseline: 2.4129x; 2.4129x over previous
#include <cuda_runtime.h>
#include <cuda_bf16.h>
#include <math.h>
#include <stdint.h>

#define BATCH 4
#define SEQ   2048
#define DM    1024
#define BS    (BATCH * SEQ)

// ---------------------------------------------------------------------------
// Scratch (allocation-free: __device__ globals)
// ---------------------------------------------------------------------------
__device__ __nv_bfloat16 g_xh[BS * DM], g_xl[BS * DM];
__device__ __nv_bfloat16 g_wth[4][DM * DM], g_wtl[4][DM * DM];   // transposed weights [N][K]
__device__ __nv_bfloat16 g_qh[BS * DM], g_ql[BS * DM];
__device__ __nv_bfloat16 g_kh[BS * DM], g_kl[BS * DM];
__device__ __nv_bfloat16 g_vh[BS * DM], g_vl[BS * DM];
__device__ __nv_bfloat16 g_vth[BS * DM], g_vtl[BS * DM];         // V transposed [B][D][S]
__device__ float         g_s[BATCH * SEQ * SEQ];                 // scores fp32 (64MB)
__device__ __nv_bfloat16 g_ph[BATCH * SEQ * SEQ], g_pl[BATCH * SEQ * SEQ];
__device__ __nv_bfloat16 g_mh[BS * DM], g_ml[BS * DM];

// ---------------------------------------------------------------------------
// Helpers
// ---------------------------------------------------------------------------
__device__ __forceinline__ uint32_t smem_u32(const void* p) {
    uint32_t a;
    asm("{ .reg .u64 t; cvta.to.shared.u64 t, %1; cvt.u32.u64 %0, t; }" : "=r"(a) : "l"(p));
    return a;
}
__device__ __forceinline__ void cp16(uint32_t dst, const void* src) {
    asm volatile("cp.async.cg.shared.global [%0], [%1], 16;" :: "r"(dst), "l"(src));
}
#define CP_COMMIT() asm volatile("cp.async.commit_group;" ::: "memory")
#define CP_WAIT2()  asm volatile("cp.async.wait_group 2;" ::: "memory")

__device__ __forceinline__ void ldm_x4(uint32_t a, uint32_t& r0, uint32_t& r1, uint32_t& r2, uint32_t& r3) {
    asm volatile("ldmatrix.sync.aligned.m8n8.x4.shared.b16 {%0,%1,%2,%3}, [%4];"
                 : "=r"(r0), "=r"(r1), "=r"(r2), "=r"(r3) : "r"(a));
}
__device__ __forceinline__ void mma16816(float* d, const uint32_t* a, const uint32_t* b) {
    asm volatile("mma.sync.aligned.m16n8k16.row.col.f32.bf16.bf16.f32 "
                 "{%0,%1,%2,%3}, {%4,%5,%6,%7}, {%8,%9}, {%0,%1,%2,%3};"
                 : "+f"(d[0]), "+f"(d[1]), "+f"(d[2]), "+f"(d[3])
                 : "r"(a[0]), "r"(a[1]), "r"(a[2]), "r"(a[3]), "r"(b[0]), "r"(b[1]));
}
__device__ __forceinline__ void split_bf16(float x, __nv_bfloat16& h, __nv_bfloat16& l) {
    h = __float2bfloat16_rn(x);
    l = __float2bfloat16_rn(x - __bfloat162float(h));
}

// ---------------------------------------------------------------------------
// Split-bf16 GEMM via mma.sync:  C = alpha*(A @ B^T) [+bias] [+resid]
//   A (hi/lo): [M,K] bf16 K-major, batch stride sA (elements)
//   B (hi/lo): [N,K] bf16 K-major, batch stride sB
// CTA tile 128x128, K-chunk 32, 3-stage cp.async pipeline, 256 threads.
// Warp grid 2(M) x 4(N): warp tile 64x32. mma m16n8k16, 3-term split product.
// SMEM rows padded to 80B (32 bf16 data + 16B pad) -> conflict-free ldmatrix.
// ---------------------------------------------------------------------------
#define BM 128
#define BN 128
#define BK 32
#define ROWB 80                         // bytes per smem row
#define ARR_B (128 * ROWB)              // 10240 bytes per operand array
#define OFF_AH 0
#define OFF_AL (1 * ARR_B)
#define OFF_BH (2 * ARR_B)
#define OFF_BL (3 * ARR_B)
#define STAGE_B (4 * ARR_B)             // 40960
#define NSTAGE 3
#define GEMM_SMEM (NSTAGE * STAGE_B)    // 122880

template<bool BIAS, bool RESID, bool WF32, bool WSPLIT>
__global__ __launch_bounds__(256, 1)
void gemm_mma(const __nv_bfloat16* __restrict__ Ah_g, const __nv_bfloat16* __restrict__ Al_g,
              const __nv_bfloat16* __restrict__ Bh_g, const __nv_bfloat16* __restrict__ Bl_g,
              const float* __restrict__ bias, const float* __restrict__ resid,
              float* __restrict__ Cf, __nv_bfloat16* __restrict__ Ch, __nv_bfloat16* __restrict__ Cl,
              int M, int N, int K, float alpha,
              long long sA, long long sB, long long sC)
{
    extern __shared__ __align__(128) char smem[];
    const uint32_t sb = smem_u32(smem);
    const int tid = threadIdx.x;
    const int wid = tid >> 5, lane = tid & 31;
    const int wm = wid & 1, wn = wid >> 1;
    const int m0 = blockIdx.y * BM;
    const int n0 = blockIdx.x * BN;
    const long long zA = (long long)blockIdx.z * sA;
    const long long zB = (long long)blockIdx.z * sB;
    const long long zC = (long long)blockIdx.z * sC;

    // loader mapping: 512 16B-segments per operand array, 2 per thread
    const int r0 = tid >> 2, c0 = tid & 3;          // seg tid
    const int r1 = (tid + 256) >> 2, c1 = c0;       // seg tid+256

    float acc[4][4][4];
    #pragma unroll
    for (int i = 0; i < 4; i++)
        #pragma unroll
        for (int j = 0; j < 4; j++)
            #pragma unroll
            for (int t = 0; t < 4; t++) acc[i][j][t] = 0.0f;

    // fragment smem offsets (stage-relative, bytes)
    const int arow = (lane & 7) + ((lane >> 3) & 1) * 8;
    const int kseg_a = lane >> 4;
    const int brow = ((lane >> 4) << 3) + (lane & 7);
    const int kseg_b = (lane >> 3) & 1;
    int aoff[4], boff[2];
    #pragma unroll
    for (int mt = 0; mt < 4; mt++) aoff[mt] = (wm * 64 + mt * 16 + arow) * ROWB + kseg_a * 16;
    #pragma unroll
    for (int p = 0; p < 2; p++)    boff[p] = (wn * 32 + p * 16 + brow) * ROWB + kseg_b * 16;

    const int nc = K / BK;

    auto issue_loads = [&](int kc) {
        char* st = smem + (kc % NSTAGE) * STAGE_B;
        const uint32_t stu = sb + (kc % NSTAGE) * STAGE_B;
        const int kb = kc * BK;
        {   // A rows
            const long long g0 = zA + (long long)(m0 + r0) * K + kb + c0 * 8;
            const long long g1 = zA + (long long)(m0 + r1) * K + kb + c1 * 8;
            const uint32_t d0 = stu + r0 * ROWB + c0 * 16;
            const uint32_t d1 = stu + r1 * ROWB + c1 * 16;
            cp16(d0 + OFF_AH, Ah_g + g0);  cp16(d0 + OFF_AL, Al_g + g0);
            cp16(d1 + OFF_AH, Ah_g + g1);  cp16(d1 + OFF_AL, Al_g + g1);
        }
        {   // B rows
            const long long g0 = zB + (long long)(n0 + r0) * K + kb + c0 * 8;
            const long long g1 = zB + (long long)(n0 + r1) * K + kb + c1 * 8;
            const uint32_t d0 = stu + r0 * ROWB + c0 * 16;
            const uint32_t d1 = stu + r1 * ROWB + c1 * 16;
            cp16(d0 + OFF_BH, Bh_g + g0);  cp16(d0 + OFF_BL, Bl_g + g0);
            cp16(d1 + OFF_BH, Bh_g + g1);  cp16(d1 + OFF_BL, Bl_g + g1);
        }
        (void)st;
    };

    // prologue: stages 0, 1
    issue_loads(0); CP_COMMIT();
    if (nc > 1) issue_loads(1);
    CP_COMMIT();

    for (int kc = 0; kc < nc; kc++) {
        __syncthreads();
        if (kc + 2 < nc) issue_loads(kc + 2);
        CP_COMMIT();
        CP_WAIT2();
        __syncthreads();

        const uint32_t stu = sb + (kc % NSTAGE) * STAGE_B;

        #pragma unroll
        for (int ks = 0; ks < 2; ks++) {
            uint32_t ah[4][4], al[4][4], bh[4][2], bl[4][2];
            #pragma unroll
            for (int mt = 0; mt < 4; mt++) {
                ldm_x4(stu + OFF_AH + aoff[mt] + ks * 32, ah[mt][0], ah[mt][1], ah[mt][2], ah[mt][3]);
                ldm_x4(stu + OFF_AL + aoff[mt] + ks * 32, al[mt][0], al[mt][1], al[mt][2], al[mt][3]);
            }
            #pragma unroll
            for (int p = 0; p < 2; p++) {
                ldm_x4(stu + OFF_BH + boff[p] + ks * 32,
                       bh[2*p][0], bh[2*p][1], bh[2*p+1][0], bh[2*p+1][1]);
                ldm_x4(stu + OFF_BL + boff[p] + ks * 32,
                       bl[2*p][0], bl[2*p][1], bl[2*p+1][0], bl[2*p+1][1]);
            }
            #pragma unroll
            for (int mt = 0; mt < 4; mt++)
                #pragma unroll
                for (int nt = 0; nt < 4; nt++) {
                    mma16816(acc[mt][nt], ah[mt], bh[nt]);
                    mma16816(acc[mt][nt], ah[mt], bl[nt]);
                    mma16816(acc[mt][nt], al[mt], bh[nt]);
                }
        }
    }

    // ---- epilogue ----
    const int gr = lane >> 2, qc = (lane & 3) * 2;
    #pragma unroll
    for (int mt = 0; mt < 4; mt++) {
        #pragma unroll
        for (int half = 0; half < 2; half++) {
            const int m = m0 + wm * 64 + mt * 16 + gr + half * 8;
            const long long crow = zC + (long long)m * N;
            #pragma unroll
            for (int nt = 0; nt < 4; nt++) {
                const int c = n0 + wn * 32 + nt * 8 + qc;
                float v0 = acc[mt][nt][half * 2 + 0] * alpha;
                float v1 = acc[mt][nt][half * 2 + 1] * alpha;
                if (BIAS)  { v0 += __ldg(&bias[c]); v1 += __ldg(&bias[c + 1]); }
                if (RESID) { v0 += resid[crow + c]; v1 += resid[crow + c + 1]; }
                if (WF32)  { *(float2*)(Cf + crow + c) = make_float2(v0, v1); }
                if (WSPLIT) {
                    __nv_bfloat16 h0, l0, h1, l1;
                    split_bf16(v0, h0, l0);
                    split_bf16(v1, h1, l1);
                    __nv_bfloat162 hh; hh.x = h0; hh.y = h1;
                    __nv_bfloat162 ll; ll.x = l0; ll.y = l1;
                    *(__nv_bfloat162*)(Ch + crow + c) = hh;
                    *(__nv_bfloat162*)(Cl + crow + c) = ll;
                }
            }
        }
    }
}

// ---------------------------------------------------------------------------
// GELU (exact erf) + split
// ---------------------------------------------------------------------------
__global__ void gelu_split_kernel(const float* __restrict__ in,
                                  __nv_bfloat16* __restrict__ oh,
                                  __nv_bfloat16* __restrict__ ol, int n)
{
    int i = blockIdx.x * blockDim.x + threadIdx.x;
    if (i < n) {
        float t = in[i];
        float g = 0.5f * t * (1.0f + erff(t * 0.70710678118654752f));
        split_bf16(g, oh[i], ol[i]);
    }
}

// ---------------------------------------------------------------------------
// Weight transpose + split:  W[K][N] fp32 -> Wt hi/lo [N][K] bf16
// ---------------------------------------------------------------------------
__global__ __launch_bounds__(256)
void wt_split_kernel(const float* __restrict__ W,
                     __nv_bfloat16* __restrict__ th, __nv_bfloat16* __restrict__ tl)
{
    __shared__ float t[32][33];
    const int n0 = blockIdx.x * 32, k0 = blockIdx.y * 32;
    const int tx = threadIdx.x, ty = threadIdx.y;
    #pragma unroll
    for (int i = 0; i < 4; i++)
        t[ty + i * 8][tx] = W[(k0 + ty + i * 8) * DM + n0 + tx];
    __syncthreads();
    #pragma unroll
    for (int i = 0; i < 4; i++) {
        float v = t[tx][ty + i * 8];
        int idx = (n0 + ty + i * 8) * DM + k0 + tx;
        split_bf16(v, th[idx], tl[idx]);
    }
}

// ---------------------------------------------------------------------------
// bf16 pair transpose:  [B][S][D] -> [B][D][S]
// ---------------------------------------------------------------------------
__global__ __launch_bounds__(256)
void t2_kernel(const __nv_bfloat16* __restrict__ ih, const __nv_bfloat16* __restrict__ il,
               __nv_bfloat16* __restrict__ oh, __nv_bfloat16* __restrict__ ol)
{
    __shared__ __nv_bfloat16 th[32][33], tl[32][33];
    const long long bi = (long long)blockIdx.z * SEQ * DM;
    const int d0 = blockIdx.x * 32, s0 = blockIdx.y * 32;
    const int tx = threadIdx.x, ty = threadIdx.y;
    #pragma unroll
    for (int i = 0; i < 4; i++) {
        int r = ty + i * 8;
        th[r][tx] = ih[bi + (long long)(s0 + r) * DM + d0 + tx];
        tl[r][tx] = il[bi + (long long)(s0 + r) * DM + d0 + tx];
    }
    __syncthreads();
    #pragma unroll
    for (int i = 0; i < 4; i++) {
        int r = ty + i * 8;
        long long o = bi + (long long)(d0 + r) * SEQ + s0 + tx;
        oh[o] = th[tx][r];
        ol[o] = tl[tx][r];
    }
}

// ---------------------------------------------------------------------------
// Softmax (register-resident) + split to bf16 hi/lo. 256 thr / row of 2048.
// ---------------------------------------------------------------------------
__global__ __launch_bounds__(256)
void softmax_split_kernel(const float* __restrict__ S,
                          __nv_bfloat16* __restrict__ ph, __nv_bfloat16* __restrict__ pl)
{
    const long long row = (long long)blockIdx.x * SEQ;
    const float* p = S + row;
    const int tid = threadIdx.x;
    __shared__ float red[8];

    float v[8];
    #pragma unroll
    for (int i = 0; i < 8; i++) v[i] = p[tid + i * 256];

    float mx = v[0];
    #pragma unroll
    for (int i = 1; i < 8; i++) mx = fmaxf(mx, v[i]);
    #pragma unroll
    for (int o = 16; o > 0; o >>= 1) mx = fmaxf(mx, __shfl_xor_sync(0xffffffffu, mx, o));
    if ((tid & 31) == 0) red[tid >> 5] = mx;
    __syncthreads();
    float rmax = red[0];
    #pragma unroll
    for (int i = 1; i < 8; i++) rmax = fmaxf(rmax, red[i]);
    __syncthreads();

    float sum = 0.0f;
    #pragma unroll
    for (int i = 0; i < 8; i++) { v[i] = __expf(v[i] - rmax); sum += v[i]; }
    #pragma unroll
    for (int o = 16; o > 0; o >>= 1) sum += __shfl_xor_sync(0xffffffffu, sum, o);
    if ((tid & 31) == 0) red[tid >> 5] = sum;
    __syncthreads();
    float rsum = 0.0f;
    #pragma unroll
    for (int i = 0; i < 8; i++) rsum += red[i];
    const float inv = 1.0f / rsum;

    #pragma unroll
    for (int i = 0; i < 8; i++) {
        float x = v[i] * inv;
        split_bf16(x, ph[row + tid + i * 256], pl[row + tid + i * 256]);
    }
}

// ---------------------------------------------------------------------------
// Launch
// ---------------------------------------------------------------------------
extern "C" void kernel_launch(void* const* d_in, const int* in_sizes, int n_in,
                              void* d_out, int out_size)
{
    const float* tokens = (const float*)d_in[0];
    const float* Wq = (const float*)d_in[1];
    const float* bq = (const float*)d_in[2];
    const float* Wk = (const float*)d_in[3];
    const float* bk = (const float*)d_in[4];
    const float* Wv = (const float*)d_in[5];
    const float* bv = (const float*)d_in[6];
    const float* Wo = (const float*)d_in[7];
    const float* bo = (const float*)d_in[8];
    float* out = (float*)d_out;

    __nv_bfloat16 *xh, *xl, *wth, *wtl, *qh, *ql, *kh, *kl, *vh, *vl, *vth, *vtl, *pph, *ppl, *mh, *ml;
    float* s;
    cudaGetSymbolAddress((void**)&xh, g_xh);   cudaGetSymbolAddress((void**)&xl, g_xl);
    cudaGetSymbolAddress((void**)&wth, g_wth); cudaGetSymbolAddress((void**)&wtl, g_wtl);
    cudaGetSymbolAddress((void**)&qh, g_qh);   cudaGetSymbolAddress((void**)&ql, g_ql);
    cudaGetSymbolAddress((void**)&kh, g_kh);   cudaGetSymbolAddress((void**)&kl, g_kl);
    cudaGetSymbolAddress((void**)&vh, g_vh);   cudaGetSymbolAddress((void**)&vl, g_vl);
    cudaGetSymbolAddress((void**)&vth, g_vth); cudaGetSymbolAddress((void**)&vtl, g_vtl);
    cudaGetSymbolAddress((void**)&s, g_s);
    cudaGetSymbolAddress((void**)&pph, g_ph);  cudaGetSymbolAddress((void**)&ppl, g_pl);
    cudaGetSymbolAddress((void**)&mh, g_mh);   cudaGetSymbolAddress((void**)&ml, g_ml);

    cudaFuncSetAttribute(gemm_mma<true,  false, false, true >, cudaFuncAttributeMaxDynamicSharedMemorySize, GEMM_SMEM);
    cudaFuncSetAttribute(gemm_mma<false, false, true,  false>, cudaFuncAttributeMaxDynamicSharedMemorySize, GEMM_SMEM);
    cudaFuncSetAttribute(gemm_mma<false, false, false, true >, cudaFuncAttributeMaxDynamicSharedMemorySize, GEMM_SMEM);
    cudaFuncSetAttribute(gemm_mma<true,  true,  true,  false>, cudaFuncAttributeMaxDynamicSharedMemorySize, GEMM_SMEM);

    const int nTok = BS * DM;
    const float scale = 1.0f / 32.0f;

    // 1) gelu + split
    gelu_split_kernel<<<(nTok + 255) / 256, 256>>>(tokens, xh, xl, nTok);

    // 2) weight transpose + split
    {
        dim3 grid(32, 32), blk(32, 8);
        wt_split_kernel<<<grid, blk>>>(Wq, wth + 0 * DM * DM, wtl + 0 * DM * DM);
        wt_split_kernel<<<grid, blk>>>(Wk, wth + 1 * DM * DM, wtl + 1 * DM * DM);
        wt_split_kernel<<<grid, blk>>>(Wv, wth + 2 * DM * DM, wtl + 2 * DM * DM);
        wt_split_kernel<<<grid, blk>>>(Wo, wth + 3 * DM * DM, wtl + 3 * DM * DM);
    }

    // 3) Q, K, V projections -> split bf16 outputs
    {
        dim3 grid(DM / BN, BS / BM, 1);
        gemm_mma<true, false, false, true><<<grid, 256, GEMM_SMEM>>>(
            xh, xl, wth + 0 * DM * DM, wtl + 0 * DM * DM, bq, nullptr,
            nullptr, qh, ql, BS, DM, DM, 1.0f, 0, 0, 0);
        gemm_mma<true, false, false, true><<<grid, 256, GEMM_SMEM>>>(
            xh, xl, wth + 1 * DM * DM, wtl + 1 * DM * DM, bk, nullptr,
            nullptr, kh, kl, BS, DM, DM, 1.0f, 0, 0, 0);
        gemm_mma<true, false, false, true><<<grid, 256, GEMM_SMEM>>>(
            xh, xl, wth + 2 * DM * DM, wtl + 2 * DM * DM, bv, nullptr,
            nullptr, vh, vl, BS, DM, DM, 1.0f, 0, 0, 0);
    }

    // 4) V transpose: [B][S][D] -> [B][D][S]
    {
        dim3 grid(DM / 32, SEQ / 32, BATCH), blk(32, 8);
        t2_kernel<<<grid, blk>>>(vh, vl, vth, vtl);
    }

    // 5) scores = scale * Q @ K^T (batched) -> fp32
    {
        dim3 grid(SEQ / BN, SEQ / BM, BATCH);
        gemm_mma<false, false, true, false><<<grid, 256, GEMM_SMEM>>>(
            qh, ql, kh, kl, nullptr, nullptr,
            s, nullptr, nullptr, SEQ, SEQ, DM, scale,
            (long long)SEQ * DM, (long long)SEQ * DM, (long long)SEQ * SEQ);
    }

    // 6) softmax + split
    softmax_split_kernel<<<BS, 256>>>(s, pph, ppl);

    // 7) mixed = attn @ V (batched, B = Vt) -> split bf16
    {
        dim3 grid(DM / BN, SEQ / BM, BATCH);
        gemm_mma<false, false, false, true><<<grid, 256, GEMM_SMEM>>>(
            pph, ppl, vth, vtl, nullptr, nullptr,
            nullptr, mh, ml, SEQ, DM, SEQ, 1.0f,
            (long long)SEQ * SEQ, (long long)DM * SEQ, (long long)SEQ * DM);
    }

    // 8) out = mixed @ Wo^T + bo + tokens
    {
        dim3 grid(DM / BN, BS / BM, 1);
        gemm_mma<true, true, true, false><<<grid, 256, GEMM_SMEM>>>(
            mh, ml, wth + 3 * DM * DM, wtl + 3 * DM * DM, bo, tokens,
            out, nullptr, nullptr, BS, DM, DM, 1.0f, 0, 0, 0);
    }
}

// round 4
// speedup vs baseline: 2.5379x; 1.0518x over previous
#include <cuda_runtime.h>
#include <cuda_bf16.h>
#include <math.h>
#include <stdint.h>

#define BATCH 4
#define SEQ   2048
#define DM    1024
#define BS    (BATCH * SEQ)

// ---------------------------------------------------------------------------
// Scratch (allocation-free: __device__ globals)
// ---------------------------------------------------------------------------
__device__ __nv_bfloat16 g_xh[BS * DM], g_xl[BS * DM];
__device__ __nv_bfloat16 g_wth[4][DM * DM], g_wtl[4][DM * DM];   // transposed weights [N][K]
__device__ __nv_bfloat16 g_qh[BS * DM], g_ql[BS * DM];
__device__ __nv_bfloat16 g_kh[BS * DM], g_kl[BS * DM];
__device__ __nv_bfloat16 g_vh[BS * DM], g_vl[BS * DM];
__device__ __nv_bfloat16 g_vth[BS * DM], g_vtl[BS * DM];         // V transposed [B][D][S]
__device__ float         g_s[BATCH * SEQ * SEQ];                 // scores fp32 (64MB)
__device__ __nv_bfloat16 g_ph[BATCH * SEQ * SEQ], g_pl[BATCH * SEQ * SEQ];
__device__ __nv_bfloat16 g_mh[BS * DM], g_ml[BS * DM];

// ---------------------------------------------------------------------------
// Helpers
// ---------------------------------------------------------------------------
__device__ __forceinline__ uint32_t smem_u32(const void* p) {
    uint32_t a;
    asm("{ .reg .u64 t; cvta.to.shared.u64 t, %1; cvt.u32.u64 %0, t; }" : "=r"(a) : "l"(p));
    return a;
}
__device__ __forceinline__ void cp16(uint32_t dst, const void* src) {
    asm volatile("cp.async.cg.shared.global [%0], [%1], 16;" :: "r"(dst), "l"(src));
}
#define CP_COMMIT() asm volatile("cp.async.commit_group;" ::: "memory")
#define CP_WAIT2()  asm volatile("cp.async.wait_group 2;" ::: "memory")

__device__ __forceinline__ void ldm_x4(uint32_t a, uint32_t& r0, uint32_t& r1, uint32_t& r2, uint32_t& r3) {
    asm volatile("ldmatrix.sync.aligned.m8n8.x4.shared.b16 {%0,%1,%2,%3}, [%4];"
                 : "=r"(r0), "=r"(r1), "=r"(r2), "=r"(r3) : "r"(a));
}
__device__ __forceinline__ void mma16816(float* d, const uint32_t* a, const uint32_t* b) {
    asm volatile("mma.sync.aligned.m16n8k16.row.col.f32.bf16.bf16.f32 "
                 "{%0,%1,%2,%3}, {%4,%5,%6,%7}, {%8,%9}, {%0,%1,%2,%3};"
                 : "+f"(d[0]), "+f"(d[1]), "+f"(d[2]), "+f"(d[3])
                 : "r"(a[0]), "r"(a[1]), "r"(a[2]), "r"(a[3]), "r"(b[0]), "r"(b[1]));
}
__device__ __forceinline__ void split_bf16(float x, __nv_bfloat16& h, __nv_bfloat16& l) {
    h = __float2bfloat16_rn(x);
    l = __float2bfloat16_rn(x - __bfloat162float(h));
}

// ---------------------------------------------------------------------------
// Split-bf16 GEMM via mma.sync:  C = alpha*(A @ B^T) [+bias] [+resid]
//   A (hi/lo): [M,K] bf16 K-major, batch stride sA (elements)
//   B (hi/lo): [N,K] bf16 K-major, batch stride sB
// CTA tile 128x256, K-chunk 32, 3-stage cp.async pipeline, 256 threads.
// Warp grid 2(M) x 4(N): warp tile 64x64. mma m16n8k16, 3-term split product.
// SMEM rows padded to 80B -> conflict-free ldmatrix.
// ---------------------------------------------------------------------------
#define BM 128
#define BN 256
#define BK 32
#define ROWB 80
#define A_ARR (128 * ROWB)              // 10240
#define B_ARR (256 * ROWB)              // 20480
#define OFF_AH 0
#define OFF_AL (A_ARR)
#define OFF_BH (2 * A_ARR)
#define OFF_BL (2 * A_ARR + B_ARR)
#define STAGE_B (2 * A_ARR + 2 * B_ARR) // 61440
#define NSTAGE 3
#define GEMM_SMEM (NSTAGE * STAGE_B)    // 184320

template<bool BIAS, bool RESID, bool WF32, bool WSPLIT>
__global__ __launch_bounds__(256, 1)
void gemm_mma(const __nv_bfloat16* __restrict__ Ah_g, const __nv_bfloat16* __restrict__ Al_g,
              const __nv_bfloat16* __restrict__ Bh_g, const __nv_bfloat16* __restrict__ Bl_g,
              const float* __restrict__ bias, const float* __restrict__ resid,
              float* __restrict__ Cf, __nv_bfloat16* __restrict__ Ch, __nv_bfloat16* __restrict__ Cl,
              int M, int N, int K, float alpha,
              long long sA, long long sB, long long sC)
{
    extern __shared__ __align__(128) char smem[];
    const uint32_t sb = smem_u32(smem);
    const int tid = threadIdx.x;
    const int wid = tid >> 5, lane = tid & 31;
    const int wm = wid & 1, wn = wid >> 1;         // wm 0..1, wn 0..3
    const int m0 = blockIdx.y * BM;
    const int n0 = blockIdx.x * BN;
    const long long zA = (long long)blockIdx.z * sA;
    const long long zB = (long long)blockIdx.z * sB;
    const long long zC = (long long)blockIdx.z * sC;

    // loader mapping: row lr (+strides), 16B column segment lc
    const int lr = tid >> 2;              // 0..63
    const int lcb = (tid & 3) * 16;       // byte offset in row
    const int lce = (tid & 3) * 8;        // element offset in row

    float acc[4][8][4];
    #pragma unroll
    for (int i = 0; i < 4; i++)
        #pragma unroll
        for (int j = 0; j < 8; j++)
            #pragma unroll
            for (int t = 0; t < 4; t++) acc[i][j][t] = 0.0f;

    // fragment smem offsets (stage-relative, bytes)
    const int arow = (lane & 7) + ((lane >> 3) & 1) * 8;
    const int kseg_a = lane >> 4;
    const int brow = ((lane >> 4) << 3) + (lane & 7);
    const int kseg_b = (lane >> 3) & 1;
    int aoff[4], boff[4];
    #pragma unroll
    for (int mt = 0; mt < 4; mt++) aoff[mt] = (wm * 64 + mt * 16 + arow) * ROWB + kseg_a * 16;
    #pragma unroll
    for (int p = 0; p < 4; p++)    boff[p] = (wn * 64 + p * 16 + brow) * ROWB + kseg_b * 16;

    const int nc = K / BK;

    auto issue_loads = [&](int kc) {
        const uint32_t stu = sb + (kc % NSTAGE) * STAGE_B;
        const int kb = kc * BK;
        // A: 128 rows, 2 per thread, hi+lo
        #pragma unroll
        for (int i = 0; i < 2; i++) {
            const int r = lr + i * 64;
            const long long g = zA + (long long)(m0 + r) * K + kb + lce;
            const uint32_t d = stu + r * ROWB + lcb;
            cp16(d + OFF_AH, Ah_g + g);
            cp16(d + OFF_AL, Al_g + g);
        }
        // B: 256 rows, 4 per thread, hi+lo
        #pragma unroll
        for (int i = 0; i < 4; i++) {
            const int r = lr + i * 64;
            const long long g = zB + (long long)(n0 + r) * K + kb + lce;
            const uint32_t d = stu + r * ROWB + lcb;
            cp16(d + OFF_BH, Bh_g + g);
            cp16(d + OFF_BL, Bl_g + g);
        }
    };

    issue_loads(0); CP_COMMIT();
    if (nc > 1) issue_loads(1);
    CP_COMMIT();

    for (int kc = 0; kc < nc; kc++) {
        __syncthreads();
        if (kc + 2 < nc) issue_loads(kc + 2);
        CP_COMMIT();
        CP_WAIT2();
        __syncthreads();

        const uint32_t stu = sb + (kc % NSTAGE) * STAGE_B;

        #pragma unroll
        for (int ks = 0; ks < 2; ks++) {
            uint32_t ah[4][4], al[4][4];
            #pragma unroll
            for (int mt = 0; mt < 4; mt++) {
                ldm_x4(stu + OFF_AH + aoff[mt] + ks * 32, ah[mt][0], ah[mt][1], ah[mt][2], ah[mt][3]);
                ldm_x4(stu + OFF_AL + aoff[mt] + ks * 32, al[mt][0], al[mt][1], al[mt][2], al[mt][3]);
            }
            #pragma unroll
            for (int p = 0; p < 4; p++) {
                uint32_t bh[2][2], bl[2][2];
                ldm_x4(stu + OFF_BH + boff[p] + ks * 32, bh[0][0], bh[0][1], bh[1][0], bh[1][1]);
                ldm_x4(stu + OFF_BL + boff[p] + ks * 32, bl[0][0], bl[0][1], bl[1][0], bl[1][1]);
                #pragma unroll
                for (int mt = 0; mt < 4; mt++) {
                    #pragma unroll
                    for (int h = 0; h < 2; h++) {
                        float* d = acc[mt][2 * p + h];
                        mma16816(d, ah[mt], bh[h]);
                        mma16816(d, ah[mt], bl[h]);
                        mma16816(d, al[mt], bh[h]);
                    }
                }
            }
        }
    }

    // ---- epilogue ----
    const int gr = lane >> 2, qc = (lane & 3) * 2;
    #pragma unroll
    for (int mt = 0; mt < 4; mt++) {
        #pragma unroll
        for (int half = 0; half < 2; half++) {
            const int m = m0 + wm * 64 + mt * 16 + gr + half * 8;
            const long long crow = zC + (long long)m * N;
            #pragma unroll
            for (int nt = 0; nt < 8; nt++) {
                const int c = n0 + wn * 64 + nt * 8 + qc;
                float v0 = acc[mt][nt][half * 2 + 0] * alpha;
                float v1 = acc[mt][nt][half * 2 + 1] * alpha;
                if (BIAS)  { v0 += __ldg(&bias[c]); v1 += __ldg(&bias[c + 1]); }
                if (RESID) { v0 += resid[crow + c]; v1 += resid[crow + c + 1]; }
                if (WF32)  { *(float2*)(Cf + crow + c) = make_float2(v0, v1); }
                if (WSPLIT) {
                    __nv_bfloat16 h0, l0, h1, l1;
                    split_bf16(v0, h0, l0);
                    split_bf16(v1, h1, l1);
                    __nv_bfloat162 hh; hh.x = h0; hh.y = h1;
                    __nv_bfloat162 ll; ll.x = l0; ll.y = l1;
                    *(__nv_bfloat162*)(Ch + crow + c) = hh;
                    *(__nv_bfloat162*)(Cl + crow + c) = ll;
                }
            }
        }
    }
}

// ---------------------------------------------------------------------------
// GELU (exact erf) + split
// ---------------------------------------------------------------------------
__global__ void gelu_split_kernel(const float* __restrict__ in,
                                  __nv_bfloat16* __restrict__ oh,
                                  __nv_bfloat16* __restrict__ ol, int n)
{
    int i = blockIdx.x * blockDim.x + threadIdx.x;
    if (i < n) {
        float t = in[i];
        float g = 0.5f * t * (1.0f + erff(t * 0.70710678118654752f));
        split_bf16(g, oh[i], ol[i]);
    }
}

// ---------------------------------------------------------------------------
// Weight transpose + split:  W[K][N] fp32 -> Wt hi/lo [N][K] bf16
// ---------------------------------------------------------------------------
__global__ __launch_bounds__(256)
void wt_split_kernel(const float* __restrict__ W,
                     __nv_bfloat16* __restrict__ th, __nv_bfloat16* __restrict__ tl)
{
    __shared__ float t[32][33];
    const int n0 = blockIdx.x * 32, k0 = blockIdx.y * 32;
    const int tx = threadIdx.x, ty = threadIdx.y;
    #pragma unroll
    for (int i = 0; i < 4; i++)
        t[ty + i * 8][tx] = W[(k0 + ty + i * 8) * DM + n0 + tx];
    __syncthreads();
    #pragma unroll
    for (int i = 0; i < 4; i++) {
        float v = t[tx][ty + i * 8];
        int idx = (n0 + ty + i * 8) * DM + k0 + tx;
        split_bf16(v, th[idx], tl[idx]);
    }
}

// ---------------------------------------------------------------------------
// bf16 pair transpose:  [B][S][D] -> [B][D][S]
// ---------------------------------------------------------------------------
__global__ __launch_bounds__(256)
void t2_kernel(const __nv_bfloat16* __restrict__ ih, const __nv_bfloat16* __restrict__ il,
               __nv_bfloat16* __restrict__ oh, __nv_bfloat16* __restrict__ ol)
{
    __shared__ __nv_bfloat16 th[32][33], tl[32][33];
    const long long bi = (long long)blockIdx.z * SEQ * DM;
    const int d0 = blockIdx.x * 32, s0 = blockIdx.y * 32;
    const int tx = threadIdx.x, ty = threadIdx.y;
    #pragma unroll
    for (int i = 0; i < 4; i++) {
        int r = ty + i * 8;
        th[r][tx] = ih[bi + (long long)(s0 + r) * DM + d0 + tx];
        tl[r][tx] = il[bi + (long long)(s0 + r) * DM + d0 + tx];
    }
    __syncthreads();
    #pragma unroll
    for (int i = 0; i < 4; i++) {
        int r = ty + i * 8;
        long long o = bi + (long long)(d0 + r) * SEQ + s0 + tx;
        oh[o] = th[tx][r];
        ol[o] = tl[tx][r];
    }
}

// ---------------------------------------------------------------------------
// Softmax (register-resident) + split to bf16 hi/lo. 256 thr / row of 2048.
// ---------------------------------------------------------------------------
__global__ __launch_bounds__(256)
void softmax_split_kernel(const float* __restrict__ S,
                          __nv_bfloat16* __restrict__ ph, __nv_bfloat16* __restrict__ pl)
{
    const long long row = (long long)blockIdx.x * SEQ;
    const float* p = S + row;
    const int tid = threadIdx.x;
    __shared__ float red[8];

    float v[8];
    #pragma unroll
    for (int i = 0; i < 8; i++) v[i] = p[tid + i * 256];

    float mx = v[0];
    #pragma unroll
    for (int i = 1; i < 8; i++) mx = fmaxf(mx, v[i]);
    #pragma unroll
    for (int o = 16; o > 0; o >>= 1) mx = fmaxf(mx, __shfl_xor_sync(0xffffffffu, mx, o));
    if ((tid & 31) == 0) red[tid >> 5] = mx;
    __syncthreads();
    float rmax = red[0];
    #pragma unroll
    for (int i = 1; i < 8; i++) rmax = fmaxf(rmax, red[i]);
    __syncthreads();

    float sum = 0.0f;
    #pragma unroll
    for (int i = 0; i < 8; i++) { v[i] = __expf(v[i] - rmax); sum += v[i]; }
    #pragma unroll
    for (int o = 16; o > 0; o >>= 1) sum += __shfl_xor_sync(0xffffffffu, sum, o);
    if ((tid & 31) == 0) red[tid >> 5] = sum;
    __syncthreads();
    float rsum = 0.0f;
    #pragma unroll
    for (int i = 0; i < 8; i++) rsum += red[i];
    const float inv = 1.0f / rsum;

    #pragma unroll
    for (int i = 0; i < 8; i++) {
        float x = v[i] * inv;
        split_bf16(x, ph[row + tid + i * 256], pl[row + tid + i * 256]);
    }
}

// ---------------------------------------------------------------------------
// Launch
// ---------------------------------------------------------------------------
extern "C" void kernel_launch(void* const* d_in, const int* in_sizes, int n_in,
                              void* d_out, int out_size)
{
    const float* tokens = (const float*)d_in[0];
    const float* Wq = (const float*)d_in[1];
    const float* bq = (const float*)d_in[2];
    const float* Wk = (const float*)d_in[3];
    const float* bk = (const float*)d_in[4];
    const float* Wv = (const float*)d_in[5];
    const float* bv = (const float*)d_in[6];
    const float* Wo = (const float*)d_in[7];
    const float* bo = (const float*)d_in[8];
    float* out = (float*)d_out;

    __nv_bfloat16 *xh, *xl, *wth, *wtl, *qh, *ql, *kh, *kl, *vh, *vl, *vth, *vtl, *pph, *ppl, *mh, *ml;
    float* s;
    cudaGetSymbolAddress((void**)&xh, g_xh);   cudaGetSymbolAddress((void**)&xl, g_xl);
    cudaGetSymbolAddress((void**)&wth, g_wth); cudaGetSymbolAddress((void**)&wtl, g_wtl);
    cudaGetSymbolAddress((void**)&qh, g_qh);   cudaGetSymbolAddress((void**)&ql, g_ql);
    cudaGetSymbolAddress((void**)&kh, g_kh);   cudaGetSymbolAddress((void**)&kl, g_kl);
    cudaGetSymbolAddress((void**)&vh, g_vh);   cudaGetSymbolAddress((void**)&vl, g_vl);
    cudaGetSymbolAddress((void**)&vth, g_vth); cudaGetSymbolAddress((void**)&vtl, g_vtl);
    cudaGetSymbolAddress((void**)&s, g_s);
    cudaGetSymbolAddress((void**)&pph, g_ph);  cudaGetSymbolAddress((void**)&ppl, g_pl);
    cudaGetSymbolAddress((void**)&mh, g_mh);   cudaGetSymbolAddress((void**)&ml, g_ml);

    cudaFuncSetAttribute(gemm_mma<true,  false, false, true >, cudaFuncAttributeMaxDynamicSharedMemorySize, GEMM_SMEM);
    cudaFuncSetAttribute(gemm_mma<false, false, true,  false>, cudaFuncAttributeMaxDynamicSharedMemorySize, GEMM_SMEM);
    cudaFuncSetAttribute(gemm_mma<false, false, false, true >, cudaFuncAttributeMaxDynamicSharedMemorySize, GEMM_SMEM);
    cudaFuncSetAttribute(gemm_mma<true,  true,  true,  false>, cudaFuncAttributeMaxDynamicSharedMemorySize, GEMM_SMEM);

    const int nTok = BS * DM;
    const float scale = 1.0f / 32.0f;

    // 1) gelu + split
    gelu_split_kernel<<<(nTok + 255) / 256, 256>>>(tokens, xh, xl, nTok);

    // 2) weight transpose + split
    {
        dim3 grid(32, 32), blk(32, 8);
        wt_split_kernel<<<grid, blk>>>(Wq, wth + 0 * DM * DM, wtl + 0 * DM * DM);
        wt_split_kernel<<<grid, blk>>>(Wk, wth + 1 * DM * DM, wtl + 1 * DM * DM);
        wt_split_kernel<<<grid, blk>>>(Wv, wth + 2 * DM * DM, wtl + 2 * DM * DM);
        wt_split_kernel<<<grid, blk>>>(Wo, wth + 3 * DM * DM, wtl + 3 * DM * DM);
    }

    // 3) Q, K, V projections -> split bf16 outputs
    {
        dim3 grid(DM / BN, BS / BM, 1);
        gemm_mma<true, false, false, true><<<grid, 256, GEMM_SMEM>>>(
            xh, xl, wth + 0 * DM * DM, wtl + 0 * DM * DM, bq, nullptr,
            nullptr, qh, ql, BS, DM, DM, 1.0f, 0, 0, 0);
        gemm_mma<true, false, false, true><<<grid, 256, GEMM_SMEM>>>(
            xh, xl, wth + 1 * DM * DM, wtl + 1 * DM * DM, bk, nullptr,
            nullptr, kh, kl, BS, DM, DM, 1.0f, 0, 0, 0);
        gemm_mma<true, false, false, true><<<grid, 256, GEMM_SMEM>>>(
            xh, xl, wth + 2 * DM * DM, wtl + 2 * DM * DM, bv, nullptr,
            nullptr, vh, vl, BS, DM, DM, 1.0f, 0, 0, 0);
    }

    // 4) V transpose: [B][S][D] -> [B][D][S]
    {
        dim3 grid(DM / 32, SEQ / 32, BATCH), blk(32, 8);
        t2_kernel<<<grid, blk>>>(vh, vl, vth, vtl);
    }

    // 5) scores = scale * Q @ K^T (batched) -> fp32
    {
        dim3 grid(SEQ / BN, SEQ / BM, BATCH);
        gemm_mma<false, false, true, false><<<grid, 256, GEMM_SMEM>>>(
            qh, ql, kh, kl, nullptr, nullptr,
            s, nullptr, nullptr, SEQ, SEQ, DM, scale,
            (long long)SEQ * DM, (long long)SEQ * DM, (long long)SEQ * SEQ);
    }

    // 6) softmax + split
    softmax_split_kernel<<<BS, 256>>>(s, pph, ppl);

    // 7) mixed = attn @ V (batched, B = Vt) -> split bf16
    {
        dim3 grid(DM / BN, SEQ / BM, BATCH);
        gemm_mma<false, false, false, true><<<grid, 256, GEMM_SMEM>>>(
            pph, ppl, vth, vtl, nullptr, nullptr,
            nullptr, mh, ml, SEQ, DM, SEQ, 1.0f,
            (long long)SEQ * SEQ, (long long)DM * SEQ, (long long)SEQ * DM);
    }

    // 8) out = mixed @ Wo^T + bo + tokens
    {
        dim3 grid(DM / BN, BS / BM, 1);
        gemm_mma<true, true, true, false><<<grid, 256, GEMM_SMEM>>>(
            mh, ml, wth + 3 * DM * DM, wtl + 3 * DM * DM, bo, tokens,
            out, nullptr, nullptr, BS, DM, DM, 1.0f, 0, 0, 0);
    }
}

// round 7
// speedup vs baseline: 3.4118x; 1.3444x over previous
#include <cuda_runtime.h>
#include <cuda_fp16.h>
#include <math.h>
#include <stdint.h>

#define BATCH 4
#define SEQ   2048
#define DM    1024
#define BS    (BATCH * SEQ)

// ---------------------------------------------------------------------------
// Scratch (allocation-free: __device__ globals)
// ---------------------------------------------------------------------------
__device__ __half g_x[BS * DM];                         // gelu(tokens), fp16 (A-side)
__device__ __half g_wth[4][DM * DM], g_wtl[4][DM * DM]; // transposed weights [N][K] hi/lo
__device__ __half g_q[BS * DM];                         // A-side
__device__ __half g_kh[BS * DM], g_kl[BS * DM];         // B-side split
__device__ __half g_vh[BS * DM], g_vl[BS * DM];
__device__ __half g_vth[BS * DM], g_vtl[BS * DM];       // V^T [B][D][S] hi/lo
__device__ float  g_s[BATCH * SEQ * SEQ];               // scores fp32 (64MB)
__device__ __half g_p[BATCH * SEQ * SEQ];               // probs fp16 (A-side)
__device__ __half g_m[BS * DM];                         // mixed fp16 (A-side)

// ---------------------------------------------------------------------------
// Helpers
// ---------------------------------------------------------------------------
__device__ __forceinline__ uint32_t smem_u32(const void* p) {
    uint32_t a;
    asm("{ .reg .u64 t; cvta.to.shared.u64 t, %1; cvt.u32.u64 %0, t; }" : "=r"(a) : "l"(p));
    return a;
}
__device__ __forceinline__ void cp16(uint32_t dst, const void* src) {
    asm volatile("cp.async.cg.shared.global [%0], [%1], 16;" :: "r"(dst), "l"(src));
}
#define CP_COMMIT() asm volatile("cp.async.commit_group;" ::: "memory")
#define CP_WAIT2()  asm volatile("cp.async.wait_group 2;" ::: "memory")

__device__ __forceinline__ void ldm_x4(uint32_t a, uint32_t& r0, uint32_t& r1, uint32_t& r2, uint32_t& r3) {
    asm volatile("ldmatrix.sync.aligned.m8n8.x4.shared.b16 {%0,%1,%2,%3}, [%4];"
                 : "=r"(r0), "=r"(r1), "=r"(r2), "=r"(r3) : "r"(a));
}
__device__ __forceinline__ void mma16816(float* d, const uint32_t* a, const uint32_t* b) {
    asm volatile("mma.sync.aligned.m16n8k16.row.col.f32.f16.f16.f32 "
                 "{%0,%1,%2,%3}, {%4,%5,%6,%7}, {%8,%9}, {%0,%1,%2,%3};"
                 : "+f"(d[0]), "+f"(d[1]), "+f"(d[2]), "+f"(d[3])
                 : "r"(a[0]), "r"(a[1]), "r"(a[2]), "r"(a[3]), "r"(b[0]), "r"(b[1]));
}
__device__ __forceinline__ void split_f16(float x, __half& h, __half& l) {
    h = __float2half_rn(x);
    l = __float2half_rn(x - __half2float(h));
}

// ---------------------------------------------------------------------------
// 2-term fp16 GEMM via mma.sync:  C = alpha*(A @ B^T) [+bias] [+resid]
//   A: [M,K] fp16 K-major (plain, rounded)
//   B (hi/lo): [N,K] fp16 K-major
// CTA tile 128x256, K-chunk 32, 3-stage cp.async pipeline, 256 threads.
// Warp grid 2(M) x 4(N): warp tile 64x64. Terms: A*Bh + A*Bl.
// SMEM rows padded to 80B -> conflict-free ldmatrix.
// ---------------------------------------------------------------------------
#define BM 128
#define BN 256
#define BK 32
#define ROWB 80
#define A_ARR (128 * ROWB)              // 10240
#define B_ARR (256 * ROWB)              // 20480
#define OFF_A  0
#define OFF_BH (A_ARR)
#define OFF_BL (A_ARR + B_ARR)
#define STAGE_B (A_ARR + 2 * B_ARR)     // 51200
#define NSTAGE 3
#define GEMM_SMEM (NSTAGE * STAGE_B)    // 153600

template<bool BIAS, bool RESID, bool WF32, bool WH, bool WSPLIT>
__global__ __launch_bounds__(256, 1)
void gemm_mma(const __half* __restrict__ A_g,
              const __half* __restrict__ Bh_g, const __half* __restrict__ Bl_g,
              const float* __restrict__ bias, const float* __restrict__ resid,
              float* __restrict__ Cf, __half* __restrict__ Ch, __half* __restrict__ Cl,
              int M, int N, int K, float alpha,
              long long sA, long long sB, long long sC)
{
    extern __shared__ __align__(128) char smem[];
    const uint32_t sb = smem_u32(smem);
    const int tid = threadIdx.x;
    const int wid = tid >> 5, lane = tid & 31;
    const int wm = wid & 1, wn = wid >> 1;
    const int m0 = blockIdx.y * BM;
    const int n0 = blockIdx.x * BN;
    const long long zA = (long long)blockIdx.z * sA;
    const long long zB = (long long)blockIdx.z * sB;
    const long long zC = (long long)blockIdx.z * sC;

    const int lr = tid >> 2;              // 0..63 row base
    const int lcb = (tid & 3) * 16;       // byte seg in row
    const int lce = (tid & 3) * 8;        // element seg in row

    float acc[4][8][4];
    #pragma unroll
    for (int i = 0; i < 4; i++)
        #pragma unroll
        for (int j = 0; j < 8; j++)
            #pragma unroll
            for (int t = 0; t < 4; t++) acc[i][j][t] = 0.0f;

    const int arow = (lane & 7) + ((lane >> 3) & 1) * 8;
    const int kseg_a = lane >> 4;
    const int brow = ((lane >> 4) << 3) + (lane & 7);
    const int kseg_b = (lane >> 3) & 1;
    int aoff[4], boff[4];
    #pragma unroll
    for (int mt = 0; mt < 4; mt++) aoff[mt] = (wm * 64 + mt * 16 + arow) * ROWB + kseg_a * 16;
    #pragma unroll
    for (int p = 0; p < 4; p++)    boff[p] = (wn * 64 + p * 16 + brow) * ROWB + kseg_b * 16;

    const int nc = K / BK;

    auto issue_loads = [&](int kc) {
        const uint32_t stu = sb + (kc % NSTAGE) * STAGE_B;
        const int kb = kc * BK;
        // A: 128 rows, 2 segs/thread
        #pragma unroll
        for (int i = 0; i < 2; i++) {
            const int r = lr + i * 64;
            const long long g = zA + (long long)(m0 + r) * K + kb + lce;
            cp16(stu + OFF_A + r * ROWB + lcb, A_g + g);
        }
        // B: 256 rows, hi+lo, 8 segs/thread
        #pragma unroll
        for (int i = 0; i < 4; i++) {
            const int r = lr + i * 64;
            const long long g = zB + (long long)(n0 + r) * K + kb + lce;
            const uint32_t d = stu + r * ROWB + lcb;
            cp16(d + OFF_BH, Bh_g + g);
            cp16(d + OFF_BL, Bl_g + g);
        }
    };

    issue_loads(0); CP_COMMIT();
    if (nc > 1) issue_loads(1);
    CP_COMMIT();

    for (int kc = 0; kc < nc; kc++) {
        __syncthreads();
        if (kc + 2 < nc) issue_loads(kc + 2);
        CP_COMMIT();
        CP_WAIT2();
        __syncthreads();

        const uint32_t stu = sb + (kc % NSTAGE) * STAGE_B;

        #pragma unroll
        for (int ks = 0; ks < 2; ks++) {
            uint32_t ah[4][4];
            #pragma unroll
            for (int mt = 0; mt < 4; mt++)
                ldm_x4(stu + OFF_A + aoff[mt] + ks * 32, ah[mt][0], ah[mt][1], ah[mt][2], ah[mt][3]);
            #pragma unroll
            for (int p = 0; p < 4; p++) {
                uint32_t bh[2][2], bl[2][2];
                ldm_x4(stu + OFF_BH + boff[p] + ks * 32, bh[0][0], bh[0][1], bh[1][0], bh[1][1]);
                ldm_x4(stu + OFF_BL + boff[p] + ks * 32, bl[0][0], bl[0][1], bl[1][0], bl[1][1]);
                #pragma unroll
                for (int mt = 0; mt < 4; mt++) {
                    #pragma unroll
                    for (int h = 0; h < 2; h++) {
                        float* d = acc[mt][2 * p + h];
                        mma16816(d, ah[mt], bh[h]);
                        mma16816(d, ah[mt], bl[h]);
                    }
                }
            }
        }
    }

    // ---- epilogue ----
    const int gr = lane >> 2, qc = (lane & 3) * 2;
    #pragma unroll
    for (int mt = 0; mt < 4; mt++) {
        #pragma unroll
        for (int half_ = 0; half_ < 2; half_++) {
            const int m = m0 + wm * 64 + mt * 16 + gr + half_ * 8;
            const long long crow = zC + (long long)m * N;
            #pragma unroll
            for (int nt = 0; nt < 8; nt++) {
                const int c = n0 + wn * 64 + nt * 8 + qc;
                float v0 = acc[mt][nt][half_ * 2 + 0] * alpha;
                float v1 = acc[mt][nt][half_ * 2 + 1] * alpha;
                if (BIAS)  { v0 += __ldg(&bias[c]); v1 += __ldg(&bias[c + 1]); }
                if (RESID) { v0 += resid[crow + c]; v1 += resid[crow + c + 1]; }
                if (WF32)  { *(float2*)(Cf + crow + c) = make_float2(v0, v1); }
                if (WH) {
                    __half2 hv; hv.x = __float2half_rn(v0); hv.y = __float2half_rn(v1);
                    *(__half2*)(Ch + crow + c) = hv;
                }
                if (WSPLIT) {
                    __half h0, l0, h1, l1;
                    split_f16(v0, h0, l0);
                    split_f16(v1, h1, l1);
                    __half2 hh; hh.x = h0; hh.y = h1;
                    __half2 ll; ll.x = l0; ll.y = l1;
                    *(__half2*)(Ch + crow + c) = hh;
                    *(__half2*)(Cl + crow + c) = ll;
                }
            }
        }
    }
}

// ---------------------------------------------------------------------------
// GELU (exact erf) -> fp16
// ---------------------------------------------------------------------------
__global__ void gelu_kernel(const float* __restrict__ in, __half* __restrict__ o, int n)
{
    int i = blockIdx.x * blockDim.x + threadIdx.x;
    if (i < n) {
        float t = in[i];
        float g = 0.5f * t * (1.0f + erff(t * 0.70710678118654752f));
        o[i] = __float2half_rn(g);
    }
}

// ---------------------------------------------------------------------------
// Weight transpose + split:  W[K][N] fp32 -> Wt hi/lo [N][K] fp16
// ---------------------------------------------------------------------------
__global__ __launch_bounds__(256)
void wt_split_kernel(const float* __restrict__ W,
                     __half* __restrict__ th, __half* __restrict__ tl)
{
    __shared__ float t[32][33];
    const int n0 = blockIdx.x * 32, k0 = blockIdx.y * 32;
    const int tx = threadIdx.x, ty = threadIdx.y;
    #pragma unroll
    for (int i = 0; i < 4; i++)
        t[ty + i * 8][tx] = W[(k0 + ty + i * 8) * DM + n0 + tx];
    __syncthreads();
    #pragma unroll
    for (int i = 0; i < 4; i++) {
        float v = t[tx][ty + i * 8];
        int idx = (n0 + ty + i * 8) * DM + k0 + tx;
        split_f16(v, th[idx], tl[idx]);
    }
}

// ---------------------------------------------------------------------------
// fp16 pair transpose:  [B][S][D] -> [B][D][S]  (hi and lo)
// ---------------------------------------------------------------------------
__global__ __launch_bounds__(256)
void t2_kernel(const __half* __restrict__ ih, const __half* __restrict__ il,
               __half* __restrict__ oh, __half* __restrict__ ol)
{
    __shared__ __half th[32][33], tl[32][33];
    const long long bi = (long long)blockIdx.z * SEQ * DM;
    const int d0 = blockIdx.x * 32, s0 = blockIdx.y * 32;
    const int tx = threadIdx.x, ty = threadIdx.y;
    #pragma unroll
    for (int i = 0; i < 4; i++) {
        int r = ty + i * 8;
        th[r][tx] = ih[bi + (long long)(s0 + r) * DM + d0 + tx];
        tl[r][tx] = il[bi + (long long)(s0 + r) * DM + d0 + tx];
    }
    __syncthreads();
    #pragma unroll
    for (int i = 0; i < 4; i++) {
        int r = ty + i * 8;
        long long o = bi + (long long)(d0 + r) * SEQ + s0 + tx;
        oh[o] = th[tx][r];
        ol[o] = tl[tx][r];
    }
}

// ---------------------------------------------------------------------------
// Softmax (register-resident) -> fp16. 256 thr / row of 2048.
// ---------------------------------------------------------------------------
__global__ __launch_bounds__(256)
void softmax_kernel(const float* __restrict__ S, __half* __restrict__ P)
{
    const long long row = (long long)blockIdx.x * SEQ;
    const float* p = S + row;
    const int tid = threadIdx.x;
    __shared__ float red[8];

    float v[8];
    #pragma unroll
    for (int i = 0; i < 8; i++) v[i] = p[tid + i * 256];

    float mx = v[0];
    #pragma unroll
    for (int i = 1; i < 8; i++) mx = fmaxf(mx, v[i]);
    #pragma unroll
    for (int o = 16; o > 0; o >>= 1) mx = fmaxf(mx, __shfl_xor_sync(0xffffffffu, mx, o));
    if ((tid & 31) == 0) red[tid >> 5] = mx;
    __syncthreads();
    float rmax = red[0];
    #pragma unroll
    for (int i = 1; i < 8; i++) rmax = fmaxf(rmax, red[i]);
    __syncthreads();

    float sum = 0.0f;
    #pragma unroll
    for (int i = 0; i < 8; i++) { v[i] = __expf(v[i] - rmax); sum += v[i]; }
    #pragma unroll
    for (int o = 16; o > 0; o >>= 1) sum += __shfl_xor_sync(0xffffffffu, sum, o);
    if ((tid & 31) == 0) red[tid >> 5] = sum;
    __syncthreads();
    float rsum = 0.0f;
    #pragma unroll
    for (int i = 0; i < 8; i++) rsum += red[i];
    const float inv = 1.0f / rsum;

    #pragma unroll
    for (int i = 0; i < 8; i++)
        P[row + tid + i * 256] = __float2half_rn(v[i] * inv);
}

// ---------------------------------------------------------------------------
// Launch
// ---------------------------------------------------------------------------
extern "C" void kernel_launch(void* const* d_in, const int* in_sizes, int n_in,
                              void* d_out, int out_size)
{
    const float* tokens = (const float*)d_in[0];
    const float* Wq = (const float*)d_in[1];
    const float* bq = (const float*)d_in[2];
    const float* Wk = (const float*)d_in[3];
    const float* bk = (const float*)d_in[4];
    const float* Wv = (const float*)d_in[5];
    const float* bv = (const float*)d_in[6];
    const float* Wo = (const float*)d_in[7];
    const float* bo = (const float*)d_in[8];
    float* out = (float*)d_out;

    __half *x, *wth, *wtl, *q, *kh, *kl, *vh, *vl, *vth, *vtl, *pp, *m;
    float* s;
    cudaGetSymbolAddress((void**)&x, g_x);
    cudaGetSymbolAddress((void**)&wth, g_wth); cudaGetSymbolAddress((void**)&wtl, g_wtl);
    cudaGetSymbolAddress((void**)&q, g_q);
    cudaGetSymbolAddress((void**)&kh, g_kh);   cudaGetSymbolAddress((void**)&kl, g_kl);
    cudaGetSymbolAddress((void**)&vh, g_vh);   cudaGetSymbolAddress((void**)&vl, g_vl);
    cudaGetSymbolAddress((void**)&vth, g_vth); cudaGetSymbolAddress((void**)&vtl, g_vtl);
    cudaGetSymbolAddress((void**)&s, g_s);
    cudaGetSymbolAddress((void**)&pp, g_p);
    cudaGetSymbolAddress((void**)&m, g_m);

    // IMPORTANT: every instantiation that gets launched needs its smem cap raised.
    cudaFuncSetAttribute(gemm_mma<true,  false, false, true,  false>, cudaFuncAttributeMaxDynamicSharedMemorySize, GEMM_SMEM);
    cudaFuncSetAttribute(gemm_mma<true,  false, false, false, true >, cudaFuncAttributeMaxDynamicSharedMemorySize, GEMM_SMEM);
    cudaFuncSetAttribute(gemm_mma<false, false, true,  false, false>, cudaFuncAttributeMaxDynamicSharedMemorySize, GEMM_SMEM);
    cudaFuncSetAttribute(gemm_mma<false, false, false, true,  false>, cudaFuncAttributeMaxDynamicSharedMemorySize, GEMM_SMEM);
    cudaFuncSetAttribute(gemm_mma<true,  true,  true,  false, false>, cudaFuncAttributeMaxDynamicSharedMemorySize, GEMM_SMEM);

    const int nTok = BS * DM;
    const float scale = 1.0f / 32.0f;

    // 1) gelu -> fp16
    gelu_kernel<<<(nTok + 255) / 256, 256>>>(tokens, x, nTok);

    // 2) weight transpose + split
    {
        dim3 grid(32, 32), blk(32, 8);
        wt_split_kernel<<<grid, blk>>>(Wq, wth + 0 * DM * DM, wtl + 0 * DM * DM);
        wt_split_kernel<<<grid, blk>>>(Wk, wth + 1 * DM * DM, wtl + 1 * DM * DM);
        wt_split_kernel<<<grid, blk>>>(Wv, wth + 2 * DM * DM, wtl + 2 * DM * DM);
        wt_split_kernel<<<grid, blk>>>(Wo, wth + 3 * DM * DM, wtl + 3 * DM * DM);
    }

    // 3) Q (plain fp16 out), K (split out), V (split out)
    {
        dim3 grid(DM / BN, BS / BM, 1);
        gemm_mma<true, false, false, true, false><<<grid, 256, GEMM_SMEM>>>(
            x, wth + 0 * DM * DM, wtl + 0 * DM * DM, bq, nullptr,
            nullptr, q, nullptr, BS, DM, DM, 1.0f, 0, 0, 0);
        gemm_mma<true, false, false, false, true><<<grid, 256, GEMM_SMEM>>>(
            x, wth + 1 * DM * DM, wtl + 1 * DM * DM, bk, nullptr,
            nullptr, kh, kl, BS, DM, DM, 1.0f, 0, 0, 0);
        gemm_mma<true, false, false, false, true><<<grid, 256, GEMM_SMEM>>>(
            x, wth + 2 * DM * DM, wtl + 2 * DM * DM, bv, nullptr,
            nullptr, vh, vl, BS, DM, DM, 1.0f, 0, 0, 0);
    }

    // 4) V transpose (hi/lo): [B][S][D] -> [B][D][S]
    {
        dim3 grid(DM / 32, SEQ / 32, BATCH), blk(32, 8);
        t2_kernel<<<grid, blk>>>(vh, vl, vth, vtl);
    }

    // 5) scores = scale * Q @ K^T (batched) -> fp32
    {
        dim3 grid(SEQ / BN, SEQ / BM, BATCH);
        gemm_mma<false, false, true, false, false><<<grid, 256, GEMM_SMEM>>>(
            q, kh, kl, nullptr, nullptr,
            s, nullptr, nullptr, SEQ, SEQ, DM, scale,
            (long long)SEQ * DM, (long long)SEQ * DM, (long long)SEQ * SEQ);
    }

    // 6) softmax -> fp16 probs
    softmax_kernel<<<BS, 256>>>(s, pp);

    // 7) mixed = attn @ V^T (batched) -> fp16
    {
        dim3 grid(DM / BN, SEQ / BM, BATCH);
        gemm_mma<false, false, false, true, false><<<grid, 256, GEMM_SMEM>>>(
            pp, vth, vtl, nullptr, nullptr,
            nullptr, m, nullptr, SEQ, DM, SEQ, 1.0f,
            (long long)SEQ * SEQ, (long long)DM * SEQ, (long long)SEQ * DM);
    }

    // 8) out = mixed @ Wo^T + bo + tokens
    {
        dim3 grid(DM / BN, BS / BM, 1);
        gemm_mma<true, true, true, false, false><<<grid, 256, GEMM_SMEM>>>(
            m, wth + 3 * DM * DM, wtl + 3 * DM * DM, bo, tokens,
            out, nullptr, nullptr, BS, DM, DM, 1.0f, 0, 0, 0);
    }
}

// round 8
// speedup vs baseline: 5.5275x; 1.6201x over previous
#include <cuda_runtime.h>
#include <cuda_fp16.h>
#include <math.h>
#include <stdint.h>

#define BATCH 4
#define SEQ   2048
#define DM    1024
#define BS    (BATCH * SEQ)

// ---------------------------------------------------------------------------
// Scratch (allocation-free: __device__ globals)
// ---------------------------------------------------------------------------
__device__ __half g_x[BS * DM];                 // gelu(tokens)
__device__ __half g_wt[4][DM * DM];             // transposed weights [N][K]
__device__ __half g_q[BS * DM];
__device__ __half g_k[BS * DM];
__device__ __half g_v[BS * DM];
__device__ __half g_vt[BS * DM];                // V^T [B][D][S]
__device__ __half g_s[BATCH * SEQ * SEQ];       // scores fp16 (32MB)
__device__ __half g_p[BATCH * SEQ * SEQ];       // probs fp16
__device__ __half g_m[BS * DM];                 // mixed fp16

// ---------------------------------------------------------------------------
// Helpers
// ---------------------------------------------------------------------------
__device__ __forceinline__ uint32_t smem_u32(const void* p) {
    uint32_t a;
    asm("{ .reg .u64 t; cvta.to.shared.u64 t, %1; cvt.u32.u64 %0, t; }" : "=r"(a) : "l"(p));
    return a;
}
__device__ __forceinline__ void cp16(uint32_t dst, const void* src) {
    asm volatile("cp.async.cg.shared.global [%0], [%1], 16;" :: "r"(dst), "l"(src));
}
#define CP_COMMIT() asm volatile("cp.async.commit_group;" ::: "memory")
#define CP_WAIT2()  asm volatile("cp.async.wait_group 2;" ::: "memory")

__device__ __forceinline__ void ldm_x4(uint32_t a, uint32_t& r0, uint32_t& r1, uint32_t& r2, uint32_t& r3) {
    asm volatile("ldmatrix.sync.aligned.m8n8.x4.shared.b16 {%0,%1,%2,%3}, [%4];"
                 : "=r"(r0), "=r"(r1), "=r"(r2), "=r"(r3) : "r"(a));
}
__device__ __forceinline__ void mma16816(float* d, const uint32_t* a, const uint32_t* b) {
    asm volatile("mma.sync.aligned.m16n8k16.row.col.f32.f16.f16.f32 "
                 "{%0,%1,%2,%3}, {%4,%5,%6,%7}, {%8,%9}, {%0,%1,%2,%3};"
                 : "+f"(d[0]), "+f"(d[1]), "+f"(d[2]), "+f"(d[3])
                 : "r"(a[0]), "r"(a[1]), "r"(a[2]), "r"(a[3]), "r"(b[0]), "r"(b[1]));
}

// ---------------------------------------------------------------------------
// Plain fp16 GEMM via mma.sync:  C = alpha*(A @ B^T) [+bias] [+resid]
//   A: [M,K] fp16 K-major, batch stride sA
//   B: [N,K] fp16 K-major, batch stride sB
// CTA tile 128x256, K-chunk 32, 3-stage cp.async pipeline, 256 threads.
// Warp grid 2(M) x 4(N): warp tile 64x64. 32 MMAs / warp / k16-step.
// SMEM rows padded to 80B -> conflict-free ldmatrix.
// ---------------------------------------------------------------------------
#define BM 128
#define BN 256
#define BK 32
#define ROWB 80
#define A_ARR (128 * ROWB)              // 10240
#define B_ARR (256 * ROWB)              // 20480
#define OFF_A  0
#define OFF_B  (A_ARR)
#define STAGE_B (A_ARR + B_ARR)         // 30720
#define NSTAGE 3
#define GEMM_SMEM (NSTAGE * STAGE_B)    // 92160

template<bool BIAS, bool RESID, bool WF32, bool WH>
__global__ __launch_bounds__(256, 1)
void gemm_mma(const __half* __restrict__ A_g, const __half* __restrict__ B_g,
              const float* __restrict__ bias, const float* __restrict__ resid,
              float* __restrict__ Cf, __half* __restrict__ Ch,
              int M, int N, int K, float alpha,
              long long sA, long long sB, long long sC)
{
    extern __shared__ __align__(128) char smem[];
    const uint32_t sb = smem_u32(smem);
    const int tid = threadIdx.x;
    const int wid = tid >> 5, lane = tid & 31;
    const int wm = wid & 1, wn = wid >> 1;
    const int m0 = blockIdx.y * BM;
    const int n0 = blockIdx.x * BN;
    const long long zA = (long long)blockIdx.z * sA;
    const long long zB = (long long)blockIdx.z * sB;
    const long long zC = (long long)blockIdx.z * sC;

    const int lr = tid >> 2;              // 0..63 row base
    const int lcb = (tid & 3) * 16;       // byte seg in row
    const int lce = (tid & 3) * 8;        // element seg in row

    float acc[4][8][4];
    #pragma unroll
    for (int i = 0; i < 4; i++)
        #pragma unroll
        for (int j = 0; j < 8; j++)
            #pragma unroll
            for (int t = 0; t < 4; t++) acc[i][j][t] = 0.0f;

    const int arow = (lane & 7) + ((lane >> 3) & 1) * 8;
    const int kseg_a = lane >> 4;
    const int brow = ((lane >> 4) << 3) + (lane & 7);
    const int kseg_b = (lane >> 3) & 1;
    int aoff[4], boff[4];
    #pragma unroll
    for (int mt = 0; mt < 4; mt++) aoff[mt] = (wm * 64 + mt * 16 + arow) * ROWB + kseg_a * 16;
    #pragma unroll
    for (int p = 0; p < 4; p++)    boff[p] = (wn * 64 + p * 16 + brow) * ROWB + kseg_b * 16;

    const int nc = K / BK;

    auto issue_loads = [&](int kc) {
        const uint32_t stu = sb + (kc % NSTAGE) * STAGE_B;
        const int kb = kc * BK;
        // A: 128 rows, 2 segs/thread
        #pragma unroll
        for (int i = 0; i < 2; i++) {
            const int r = lr + i * 64;
            const long long g = zA + (long long)(m0 + r) * K + kb + lce;
            cp16(stu + OFF_A + r * ROWB + lcb, A_g + g);
        }
        // B: 256 rows, 4 segs/thread
        #pragma unroll
        for (int i = 0; i < 4; i++) {
            const int r = lr + i * 64;
            const long long g = zB + (long long)(n0 + r) * K + kb + lce;
            cp16(stu + OFF_B + r * ROWB + lcb, B_g + g);
        }
    };

    issue_loads(0); CP_COMMIT();
    if (nc > 1) issue_loads(1);
    CP_COMMIT();

    for (int kc = 0; kc < nc; kc++) {
        __syncthreads();
        if (kc + 2 < nc) issue_loads(kc + 2);
        CP_COMMIT();
        CP_WAIT2();
        __syncthreads();

        const uint32_t stu = sb + (kc % NSTAGE) * STAGE_B;

        #pragma unroll
        for (int ks = 0; ks < 2; ks++) {
            uint32_t ah[4][4];
            #pragma unroll
            for (int mt = 0; mt < 4; mt++)
                ldm_x4(stu + OFF_A + aoff[mt] + ks * 32, ah[mt][0], ah[mt][1], ah[mt][2], ah[mt][3]);
            #pragma unroll
            for (int p = 0; p < 4; p++) {
                uint32_t b[2][2];
                ldm_x4(stu + OFF_B + boff[p] + ks * 32, b[0][0], b[0][1], b[1][0], b[1][1]);
                #pragma unroll
                for (int mt = 0; mt < 4; mt++) {
                    mma16816(acc[mt][2 * p + 0], ah[mt], b[0]);
                    mma16816(acc[mt][2 * p + 1], ah[mt], b[1]);
                }
            }
        }
    }

    // ---- epilogue ----
    const int gr = lane >> 2, qc = (lane & 3) * 2;
    #pragma unroll
    for (int mt = 0; mt < 4; mt++) {
        #pragma unroll
        for (int half_ = 0; half_ < 2; half_++) {
            const int m = m0 + wm * 64 + mt * 16 + gr + half_ * 8;
            const long long crow = zC + (long long)m * N;
            #pragma unroll
            for (int nt = 0; nt < 8; nt++) {
                const int c = n0 + wn * 64 + nt * 8 + qc;
                float v0 = acc[mt][nt][half_ * 2 + 0] * alpha;
                float v1 = acc[mt][nt][half_ * 2 + 1] * alpha;
                if (BIAS)  { v0 += __ldg(&bias[c]); v1 += __ldg(&bias[c + 1]); }
                if (RESID) { v0 += resid[crow + c]; v1 += resid[crow + c + 1]; }
                if (WF32)  { *(float2*)(Cf + crow + c) = make_float2(v0, v1); }
                if (WH) {
                    __half2 hv; hv.x = __float2half_rn(v0); hv.y = __float2half_rn(v1);
                    *(__half2*)(Ch + crow + c) = hv;
                }
            }
        }
    }
}

// ---------------------------------------------------------------------------
// GELU (exact erf) -> fp16
// ---------------------------------------------------------------------------
__global__ void gelu_kernel(const float* __restrict__ in, __half* __restrict__ o, int n)
{
    int i = blockIdx.x * blockDim.x + threadIdx.x;
    if (i < n) {
        float t = in[i];
        float g = 0.5f * t * (1.0f + erff(t * 0.70710678118654752f));
        o[i] = __float2half_rn(g);
    }
}

// ---------------------------------------------------------------------------
// Weight transpose:  W[K][N] fp32 -> Wt [N][K] fp16
// ---------------------------------------------------------------------------
__global__ __launch_bounds__(256)
void wt_kernel(const float* __restrict__ W, __half* __restrict__ T)
{
    __shared__ float t[32][33];
    const int n0 = blockIdx.x * 32, k0 = blockIdx.y * 32;
    const int tx = threadIdx.x, ty = threadIdx.y;
    #pragma unroll
    for (int i = 0; i < 4; i++)
        t[ty + i * 8][tx] = W[(k0 + ty + i * 8) * DM + n0 + tx];
    __syncthreads();
    #pragma unroll
    for (int i = 0; i < 4; i++)
        T[(n0 + ty + i * 8) * DM + k0 + tx] = __float2half_rn(t[tx][ty + i * 8]);
}

// ---------------------------------------------------------------------------
// fp16 transpose:  [B][S][D] -> [B][D][S]
// ---------------------------------------------------------------------------
__global__ __launch_bounds__(256)
void t1_kernel(const __half* __restrict__ in, __half* __restrict__ o)
{
    __shared__ __half t[32][33];
    const long long bi = (long long)blockIdx.z * SEQ * DM;
    const int d0 = blockIdx.x * 32, s0 = blockIdx.y * 32;
    const int tx = threadIdx.x, ty = threadIdx.y;
    #pragma unroll
    for (int i = 0; i < 4; i++) {
        int r = ty + i * 8;
        t[r][tx] = in[bi + (long long)(s0 + r) * DM + d0 + tx];
    }
    __syncthreads();
    #pragma unroll
    for (int i = 0; i < 4; i++) {
        int r = ty + i * 8;
        o[bi + (long long)(d0 + r) * SEQ + s0 + tx] = t[tx][r];
    }
}

// ---------------------------------------------------------------------------
// Softmax over fp16 scores -> fp16 probs. 256 thr / row of 2048.
// ---------------------------------------------------------------------------
__global__ __launch_bounds__(256)
void softmax_kernel(const __half* __restrict__ S, __half* __restrict__ P)
{
    const long long row = (long long)blockIdx.x * SEQ;
    const int tid = threadIdx.x;
    __shared__ float red[8];

    float v[8];
    #pragma unroll
    for (int i = 0; i < 8; i++) v[i] = __half2float(S[row + tid + i * 256]);

    float mx = v[0];
    #pragma unroll
    for (int i = 1; i < 8; i++) mx = fmaxf(mx, v[i]);
    #pragma unroll
    for (int o = 16; o > 0; o >>= 1) mx = fmaxf(mx, __shfl_xor_sync(0xffffffffu, mx, o));
    if ((tid & 31) == 0) red[tid >> 5] = mx;
    __syncthreads();
    float rmax = red[0];
    #pragma unroll
    for (int i = 1; i < 8; i++) rmax = fmaxf(rmax, red[i]);
    __syncthreads();

    float sum = 0.0f;
    #pragma unroll
    for (int i = 0; i < 8; i++) { v[i] = __expf(v[i] - rmax); sum += v[i]; }
    #pragma unroll
    for (int o = 16; o > 0; o >>= 1) sum += __shfl_xor_sync(0xffffffffu, sum, o);
    if ((tid & 31) == 0) red[tid >> 5] = sum;
    __syncthreads();
    float rsum = 0.0f;
    #pragma unroll
    for (int i = 0; i < 8; i++) rsum += red[i];
    const float inv = 1.0f / rsum;

    #pragma unroll
    for (int i = 0; i < 8; i++)
        P[row + tid + i * 256] = __float2half_rn(v[i] * inv);
}

// ---------------------------------------------------------------------------
// Launch
// ---------------------------------------------------------------------------
extern "C" void kernel_launch(void* const* d_in, const int* in_sizes, int n_in,
                              void* d_out, int out_size)
{
    const float* tokens = (const float*)d_in[0];
    const float* Wq = (const float*)d_in[1];
    const float* bq = (const float*)d_in[2];
    const float* Wk = (const float*)d_in[3];
    const float* bk = (const float*)d_in[4];
    const float* Wv = (const float*)d_in[5];
    const float* bv = (const float*)d_in[6];
    const float* Wo = (const float*)d_in[7];
    const float* bo = (const float*)d_in[8];
    float* out = (float*)d_out;

    __half *x, *wt, *q, *k, *v, *vt, *s, *pp, *m;
    cudaGetSymbolAddress((void**)&x, g_x);
    cudaGetSymbolAddress((void**)&wt, g_wt);
    cudaGetSymbolAddress((void**)&q, g_q);
    cudaGetSymbolAddress((void**)&k, g_k);
    cudaGetSymbolAddress((void**)&v, g_v);
    cudaGetSymbolAddress((void**)&vt, g_vt);
    cudaGetSymbolAddress((void**)&s, g_s);
    cudaGetSymbolAddress((void**)&pp, g_p);
    cudaGetSymbolAddress((void**)&m, g_m);

    // raise smem cap on every launched instantiation
    cudaFuncSetAttribute(gemm_mma<true,  false, false, true >, cudaFuncAttributeMaxDynamicSharedMemorySize, GEMM_SMEM);
    cudaFuncSetAttribute(gemm_mma<false, false, false, true >, cudaFuncAttributeMaxDynamicSharedMemorySize, GEMM_SMEM);
    cudaFuncSetAttribute(gemm_mma<true,  true,  true,  false>, cudaFuncAttributeMaxDynamicSharedMemorySize, GEMM_SMEM);

    const int nTok = BS * DM;
    const float scale = 1.0f / 32.0f;

    // 1) gelu -> fp16
    gelu_kernel<<<(nTok + 255) / 256, 256>>>(tokens, x, nTok);

    // 2) weight transposes -> fp16
    {
        dim3 grid(32, 32), blk(32, 8);
        wt_kernel<<<grid, blk>>>(Wq, wt + 0 * DM * DM);
        wt_kernel<<<grid, blk>>>(Wk, wt + 1 * DM * DM);
        wt_kernel<<<grid, blk>>>(Wv, wt + 2 * DM * DM);
        wt_kernel<<<grid, blk>>>(Wo, wt + 3 * DM * DM);
    }

    // 3) Q, K, V projections -> fp16
    {
        dim3 grid(DM / BN, BS / BM, 1);
        gemm_mma<true, false, false, true><<<grid, 256, GEMM_SMEM>>>(
            x, wt + 0 * DM * DM, bq, nullptr, nullptr, q, BS, DM, DM, 1.0f, 0, 0, 0);
        gemm_mma<true, false, false, true><<<grid, 256, GEMM_SMEM>>>(
            x, wt + 1 * DM * DM, bk, nullptr, nullptr, k, BS, DM, DM, 1.0f, 0, 0, 0);
        gemm_mma<true, false, false, true><<<grid, 256, GEMM_SMEM>>>(
            x, wt + 2 * DM * DM, bv, nullptr, nullptr, v, BS, DM, DM, 1.0f, 0, 0, 0);
    }

    // 4) V transpose: [B][S][D] -> [B][D][S]
    {
        dim3 grid(DM / 32, SEQ / 32, BATCH), blk(32, 8);
        t1_kernel<<<grid, blk>>>(v, vt);
    }

    // 5) scores = scale * Q @ K^T (batched) -> fp16
    {
        dim3 grid(SEQ / BN, SEQ / BM, BATCH);
        gemm_mma<false, false, false, true><<<grid, 256, GEMM_SMEM>>>(
            q, k, nullptr, nullptr, nullptr, s, SEQ, SEQ, DM, scale,
            (long long)SEQ * DM, (long long)SEQ * DM, (long long)SEQ * SEQ);
    }

    // 6) softmax -> fp16 probs
    softmax_kernel<<<BS, 256>>>(s, pp);

    // 7) mixed = attn @ V^T (batched) -> fp16
    {
        dim3 grid(DM / BN, SEQ / BM, BATCH);
        gemm_mma<false, false, false, true><<<grid, 256, GEMM_SMEM>>>(
            pp, vt, nullptr, nullptr, nullptr, m, SEQ, DM, SEQ, 1.0f,
            (long long)SEQ * SEQ, (long long)DM * SEQ, (long long)SEQ * DM);
    }

    // 8) out = mixed @ Wo^T + bo + tokens -> fp32
    {
        dim3 grid(DM / BN, BS / BM, 1);
        gemm_mma<true, true, true, false><<<grid, 256, GEMM_SMEM>>>(
            m, wt + 3 * DM * DM, bo, tokens, out, nullptr, BS, DM, DM, 1.0f, 0, 0, 0);
    }
}

// round 9
// speedup vs baseline: 6.4908x; 1.1743x over previous
#include <cuda_runtime.h>
#include <cuda_fp16.h>
#include <math.h>
#include <stdint.h>

#define BATCH 4
#define SEQ   2048
#define DM    1024
#define BS    (BATCH * SEQ)

// ---------------------------------------------------------------------------
// Scratch (allocation-free: __device__ globals)
// ---------------------------------------------------------------------------
__device__ __half g_x[BS * DM];                 // gelu(tokens)
__device__ __half g_wt[4][DM * DM];             // transposed weights [N][K]
__device__ __half g_q[BS * DM];
__device__ __half g_k[BS * DM];
__device__ __half g_v[BS * DM];
__device__ __half g_vt[BS * DM];                // V^T [B][D][S]
__device__ __half g_s[BATCH * SEQ * SEQ];       // scores fp16 (32MB)
__device__ __half g_p[BATCH * SEQ * SEQ];       // probs fp16
__device__ __half g_m[BS * DM];                 // mixed fp16

// ---------------------------------------------------------------------------
// Helpers
// ---------------------------------------------------------------------------
__device__ __forceinline__ uint32_t smem_u32(const void* p) {
    uint32_t a;
    asm("{ .reg .u64 t; cvta.to.shared.u64 t, %1; cvt.u32.u64 %0, t; }" : "=r"(a) : "l"(p));
    return a;
}
__device__ __forceinline__ void cp16(uint32_t dst, const void* src) {
    asm volatile("cp.async.cg.shared.global [%0], [%1], 16;" :: "r"(dst), "l"(src));
}
#define CP_COMMIT() asm volatile("cp.async.commit_group;" ::: "memory")
#define CP_WAIT2()  asm volatile("cp.async.wait_group 2;" ::: "memory")

__device__ __forceinline__ void ldm_x4(uint32_t a, uint32_t& r0, uint32_t& r1, uint32_t& r2, uint32_t& r3) {
    asm volatile("ldmatrix.sync.aligned.m8n8.x4.shared.b16 {%0,%1,%2,%3}, [%4];"
                 : "=r"(r0), "=r"(r1), "=r"(r2), "=r"(r3) : "r"(a));
}
__device__ __forceinline__ void mma16816(float* d, const uint32_t* a, const uint32_t* b) {
    asm volatile("mma.sync.aligned.m16n8k16.row.col.f32.f16.f16.f32 "
                 "{%0,%1,%2,%3}, {%4,%5,%6,%7}, {%8,%9}, {%0,%1,%2,%3};"
                 : "+f"(d[0]), "+f"(d[1]), "+f"(d[2]), "+f"(d[3])
                 : "r"(a[0]), "r"(a[1]), "r"(a[2]), "r"(a[3]), "r"(b[0]), "r"(b[1]));
}

// ---------------------------------------------------------------------------
// Plain fp16 GEMM via mma.sync:  C = alpha*(A @ B^T) [+bias] [+resid]
//   A: [M,K] fp16 K-major, batch stride sA
//   B: [N,K] fp16 K-major, batch stride sB
// CTA tile 128x256, K-chunk 64, 3-stage cp.async pipeline, 256 threads.
// Warp grid 2(M) x 4(N): warp tile 64x64. 32 MMAs / warp / k16-step.
// SMEM rows 128B data + 16B pad = 144B -> conflict-free ldmatrix.
// ---------------------------------------------------------------------------
#define BM 128
#define BN 256
#define BK 64
#define ROWB 144
#define A_ARR (128 * ROWB)              // 18432
#define B_ARR (256 * ROWB)              // 36864
#define OFF_A  0
#define OFF_B  (A_ARR)
#define STAGE_B (A_ARR + B_ARR)         // 55296
#define NSTAGE 3
#define GEMM_SMEM (NSTAGE * STAGE_B)    // 165888

template<bool BIAS, bool RESID, bool WF32, bool WH>
__global__ __launch_bounds__(256, 1)
void gemm_mma(const __half* __restrict__ A_g, const __half* __restrict__ B_g,
              const float* __restrict__ bias, const float* __restrict__ resid,
              float* __restrict__ Cf, __half* __restrict__ Ch,
              int M, int N, int K, float alpha,
              long long sA, long long sB, long long sC)
{
    extern __shared__ __align__(128) char smem[];
    const uint32_t sb = smem_u32(smem);
    const int tid = threadIdx.x;
    const int wid = tid >> 5, lane = tid & 31;
    const int wm = wid & 1, wn = wid >> 1;
    const int m0 = blockIdx.y * BM;
    const int n0 = blockIdx.x * BN;
    const long long zA = (long long)blockIdx.z * sA;
    const long long zB = (long long)blockIdx.z * sB;
    const long long zC = (long long)blockIdx.z * sC;

    // loader mapping: 8 x 16B segments per 128B row
    const int lr = tid >> 3;              // 0..31 row base
    const int lcb = (tid & 7) * 16;       // byte seg in row
    const int lce = (tid & 7) * 8;        // element seg in row

    float acc[4][8][4];
    #pragma unroll
    for (int i = 0; i < 4; i++)
        #pragma unroll
        for (int j = 0; j < 8; j++)
            #pragma unroll
            for (int t = 0; t < 4; t++) acc[i][j][t] = 0.0f;

    const int arow = (lane & 7) + ((lane >> 3) & 1) * 8;
    const int kseg_a = lane >> 4;
    const int brow = ((lane >> 4) << 3) + (lane & 7);
    const int kseg_b = (lane >> 3) & 1;
    int aoff[4], boff[4];
    #pragma unroll
    for (int mt = 0; mt < 4; mt++) aoff[mt] = (wm * 64 + mt * 16 + arow) * ROWB + kseg_a * 16;
    #pragma unroll
    for (int p = 0; p < 4; p++)    boff[p] = (wn * 64 + p * 16 + brow) * ROWB + kseg_b * 16;

    const int nc = K / BK;

    auto issue_loads = [&](int kc) {
        const uint32_t stu = sb + (kc % NSTAGE) * STAGE_B;
        const int kb = kc * BK;
        // A: 128 rows x 8 segs = 1024 segs, 4 per thread
        #pragma unroll
        for (int i = 0; i < 4; i++) {
            const int r = lr + i * 32;
            const long long g = zA + (long long)(m0 + r) * K + kb + lce;
            cp16(stu + OFF_A + r * ROWB + lcb, A_g + g);
        }
        // B: 256 rows x 8 segs = 2048 segs, 8 per thread
        #pragma unroll
        for (int i = 0; i < 8; i++) {
            const int r = lr + i * 32;
            const long long g = zB + (long long)(n0 + r) * K + kb + lce;
            cp16(stu + OFF_B + r * ROWB + lcb, B_g + g);
        }
    };

    issue_loads(0); CP_COMMIT();
    if (nc > 1) issue_loads(1);
    CP_COMMIT();

    for (int kc = 0; kc < nc; kc++) {
        __syncthreads();
        if (kc + 2 < nc) issue_loads(kc + 2);
        CP_COMMIT();
        CP_WAIT2();
        __syncthreads();

        const uint32_t stu = sb + (kc % NSTAGE) * STAGE_B;

        #pragma unroll
        for (int ks = 0; ks < 4; ks++) {
            uint32_t ah[4][4];
            #pragma unroll
            for (int mt = 0; mt < 4; mt++)
                ldm_x4(stu + OFF_A + aoff[mt] + ks * 32, ah[mt][0], ah[mt][1], ah[mt][2], ah[mt][3]);
            #pragma unroll
            for (int p = 0; p < 4; p++) {
                uint32_t b[2][2];
                ldm_x4(stu + OFF_B + boff[p] + ks * 32, b[0][0], b[0][1], b[1][0], b[1][1]);
                #pragma unroll
                for (int mt = 0; mt < 4; mt++) {
                    mma16816(acc[mt][2 * p + 0], ah[mt], b[0]);
                    mma16816(acc[mt][2 * p + 1], ah[mt], b[1]);
                }
            }
        }
    }

    // ---- epilogue ----
    const int gr = lane >> 2, qc = (lane & 3) * 2;
    #pragma unroll
    for (int mt = 0; mt < 4; mt++) {
        #pragma unroll
        for (int half_ = 0; half_ < 2; half_++) {
            const int m = m0 + wm * 64 + mt * 16 + gr + half_ * 8;
            const long long crow = zC + (long long)m * N;
            #pragma unroll
            for (int nt = 0; nt < 8; nt++) {
                const int c = n0 + wn * 64 + nt * 8 + qc;
                float v0 = acc[mt][nt][half_ * 2 + 0] * alpha;
                float v1 = acc[mt][nt][half_ * 2 + 1] * alpha;
                if (BIAS)  { v0 += __ldg(&bias[c]); v1 += __ldg(&bias[c + 1]); }
                if (RESID) { v0 += resid[crow + c]; v1 += resid[crow + c + 1]; }
                if (WF32)  { *(float2*)(Cf + crow + c) = make_float2(v0, v1); }
                if (WH) {
                    __half2 hv; hv.x = __float2half_rn(v0); hv.y = __float2half_rn(v1);
                    *(__half2*)(Ch + crow + c) = hv;
                }
            }
        }
    }
}

// ---------------------------------------------------------------------------
// GELU (exact erf) -> fp16
// ---------------------------------------------------------------------------
__global__ void gelu_kernel(const float* __restrict__ in, __half* __restrict__ o, int n)
{
    int i = blockIdx.x * blockDim.x + threadIdx.x;
    if (i < n) {
        float t = in[i];
        float g = 0.5f * t * (1.0f + erff(t * 0.70710678118654752f));
        o[i] = __float2half_rn(g);
    }
}

// ---------------------------------------------------------------------------
// Weight transpose:  W[K][N] fp32 -> Wt [N][K] fp16
// ---------------------------------------------------------------------------
__global__ __launch_bounds__(256)
void wt_kernel(const float* __restrict__ W, __half* __restrict__ T)
{
    __shared__ float t[32][33];
    const int n0 = blockIdx.x * 32, k0 = blockIdx.y * 32;
    const int tx = threadIdx.x, ty = threadIdx.y;
    #pragma unroll
    for (int i = 0; i < 4; i++)
        t[ty + i * 8][tx] = W[(k0 + ty + i * 8) * DM + n0 + tx];
    __syncthreads();
    #pragma unroll
    for (int i = 0; i < 4; i++)
        T[(n0 + ty + i * 8) * DM + k0 + tx] = __float2half_rn(t[tx][ty + i * 8]);
}

// ---------------------------------------------------------------------------
// fp16 transpose:  [B][S][D] -> [B][D][S]
// ---------------------------------------------------------------------------
__global__ __launch_bounds__(256)
void t1_kernel(const __half* __restrict__ in, __half* __restrict__ o)
{
    __shared__ __half t[32][33];
    const long long bi = (long long)blockIdx.z * SEQ * DM;
    const int d0 = blockIdx.x * 32, s0 = blockIdx.y * 32;
    const int tx = threadIdx.x, ty = threadIdx.y;
    #pragma unroll
    for (int i = 0; i < 4; i++) {
        int r = ty + i * 8;
        t[r][tx] = in[bi + (long long)(s0 + r) * DM + d0 + tx];
    }
    __syncthreads();
    #pragma unroll
    for (int i = 0; i < 4; i++) {
        int r = ty + i * 8;
        o[bi + (long long)(d0 + r) * SEQ + s0 + tx] = t[tx][r];
    }
}

// ---------------------------------------------------------------------------
// Softmax over fp16 scores -> fp16 probs. 256 thr / row of 2048.
// ---------------------------------------------------------------------------
__global__ __launch_bounds__(256)
void softmax_kernel(const __half* __restrict__ S, __half* __restrict__ P)
{
    const long long row = (long long)blockIdx.x * SEQ;
    const int tid = threadIdx.x;
    __shared__ float red[8];

    float v[8];
    #pragma unroll
    for (int i = 0; i < 8; i++) v[i] = __half2float(S[row + tid + i * 256]);

    float mx = v[0];
    #pragma unroll
    for (int i = 1; i < 8; i++) mx = fmaxf(mx, v[i]);
    #pragma unroll
    for (int o = 16; o > 0; o >>= 1) mx = fmaxf(mx, __shfl_xor_sync(0xffffffffu, mx, o));
    if ((tid & 31) == 0) red[tid >> 5] = mx;
    __syncthreads();
    float rmax = red[0];
    #pragma unroll
    for (int i = 1; i < 8; i++) rmax = fmaxf(rmax, red[i]);
    __syncthreads();

    float sum = 0.0f;
    #pragma unroll
    for (int i = 0; i < 8; i++) { v[i] = __expf(v[i] - rmax); sum += v[i]; }
    #pragma unroll
    for (int o = 16; o > 0; o >>= 1) sum += __shfl_xor_sync(0xffffffffu, sum, o);
    if ((tid & 31) == 0) red[tid >> 5] = sum;
    __syncthreads();
    float rsum = 0.0f;
    #pragma unroll
    for (int i = 0; i < 8; i++) rsum += red[i];
    const float inv = 1.0f / rsum;

    #pragma unroll
    for (int i = 0; i < 8; i++)
        P[row + tid + i * 256] = __float2half_rn(v[i] * inv);
}

// ---------------------------------------------------------------------------
// Launch
// ---------------------------------------------------------------------------
extern "C" void kernel_launch(void* const* d_in, const int* in_sizes, int n_in,
                              void* d_out, int out_size)
{
    const float* tokens = (const float*)d_in[0];
    const float* Wq = (const float*)d_in[1];
    const float* bq = (const float*)d_in[2];
    const float* Wk = (const float*)d_in[3];
    const float* bk = (const float*)d_in[4];
    const float* Wv = (const float*)d_in[5];
    const float* bv = (const float*)d_in[6];
    const float* Wo = (const float*)d_in[7];
    const float* bo = (const float*)d_in[8];
    float* out = (float*)d_out;

    __half *x, *wt, *q, *k, *v, *vt, *s, *pp, *m;
    cudaGetSymbolAddress((void**)&x, g_x);
    cudaGetSymbolAddress((void**)&wt, g_wt);
    cudaGetSymbolAddress((void**)&q, g_q);
    cudaGetSymbolAddress((void**)&k, g_k);
    cudaGetSymbolAddress((void**)&v, g_v);
    cudaGetSymbolAddress((void**)&vt, g_vt);
    cudaGetSymbolAddress((void**)&s, g_s);
    cudaGetSymbolAddress((void**)&pp, g_p);
    cudaGetSymbolAddress((void**)&m, g_m);

    // raise smem cap on every launched instantiation
    cudaFuncSetAttribute(gemm_mma<true,  false, false, true >, cudaFuncAttributeMaxDynamicSharedMemorySize, GEMM_SMEM);
    cudaFuncSetAttribute(gemm_mma<false, false, false, true >, cudaFuncAttributeMaxDynamicSharedMemorySize, GEMM_SMEM);
    cudaFuncSetAttribute(gemm_mma<true,  true,  true,  false>, cudaFuncAttributeMaxDynamicSharedMemorySize, GEMM_SMEM);

    const int nTok = BS * DM;
    const float scale = 1.0f / 32.0f;

    // 1) gelu -> fp16
    gelu_kernel<<<(nTok + 255) / 256, 256>>>(tokens, x, nTok);

    // 2) weight transposes -> fp16
    {
        dim3 grid(32, 32), blk(32, 8);
        wt_kernel<<<grid, blk>>>(Wq, wt + 0 * DM * DM);
        wt_kernel<<<grid, blk>>>(Wk, wt + 1 * DM * DM);
        wt_kernel<<<grid, blk>>>(Wv, wt + 2 * DM * DM);
        wt_kernel<<<grid, blk>>>(Wo, wt + 3 * DM * DM);
    }

    // 3) Q, K, V projections -> fp16
    {
        dim3 grid(DM / BN, BS / BM, 1);
        gemm_mma<true, false, false, true><<<grid, 256, GEMM_SMEM>>>(
            x, wt + 0 * DM * DM, bq, nullptr, nullptr, q, BS, DM, DM, 1.0f, 0, 0, 0);
        gemm_mma<true, false, false, true><<<grid, 256, GEMM_SMEM>>>(
            x, wt + 1 * DM * DM, bk, nullptr, nullptr, k, BS, DM, DM, 1.0f, 0, 0, 0);
        gemm_mma<true, false, false, true><<<grid, 256, GEMM_SMEM>>>(
            x, wt + 2 * DM * DM, bv, nullptr, nullptr, v, BS, DM, DM, 1.0f, 0, 0, 0);
    }

    // 4) V transpose: [B][S][D] -> [B][D][S]
    {
        dim3 grid(DM / 32, SEQ / 32, BATCH), blk(32, 8);
        t1_kernel<<<grid, blk>>>(v, vt);
    }

    // 5) scores = scale * Q @ K^T (batched) -> fp16
    {
        dim3 grid(SEQ / BN, SEQ / BM, BATCH);
        gemm_mma<false, false, false, true><<<grid, 256, GEMM_SMEM>>>(
            q, k, nullptr, nullptr, nullptr, s, SEQ, SEQ, DM, scale,
            (long long)SEQ * DM, (long long)SEQ * DM, (long long)SEQ * SEQ);
    }

    // 6) softmax -> fp16 probs
    softmax_kernel<<<BS, 256>>>(s, pp);

    // 7) mixed = attn @ V^T (batched) -> fp16
    {
        dim3 grid(DM / BN, SEQ / BM, BATCH);
        gemm_mma<false, false, false, true><<<grid, 256, GEMM_SMEM>>>(
            pp, vt, nullptr, nullptr, nullptr, m, SEQ, DM, SEQ, 1.0f,
            (long long)SEQ * SEQ, (long long)DM * SEQ, (long long)SEQ * DM);
    }

    // 8) out = mixed @ Wo^T + bo + tokens -> fp32
    {
        dim3 grid(DM / BN, BS / BM, 1);
        gemm_mma<true, true, true, false><<<grid, 256, GEMM_SMEM>>>(
            m, wt + 3 * DM * DM, bo, tokens, out, nullptr, BS, DM, DM, 1.0f, 0, 0, 0);
    }
}

// round 10
// speedup vs baseline: 6.7009x; 1.0324x over previous
#include <cuda_runtime.h>
#include <cuda_fp16.h>
#include <math.h>
#include <stdint.h>

#define BATCH 4
#define SEQ   2048
#define DM    1024
#define BS    (BATCH * SEQ)

// ---------------------------------------------------------------------------
// Scratch (allocation-free: __device__ globals)
// ---------------------------------------------------------------------------
__device__ __half g_x[BS * DM];                 // gelu(tokens)
__device__ __half g_wt[4][DM * DM];             // transposed weights [N][K]
__device__ __half g_q[BS * DM];
__device__ __half g_k[BS * DM];
__device__ __half g_v[BS * DM];
__device__ __half g_s[BATCH * SEQ * SEQ];       // scores fp16 (32MB)
__device__ __half g_p[BATCH * SEQ * SEQ];       // probs fp16
__device__ __half g_m[BS * DM];                 // mixed fp16

// ---------------------------------------------------------------------------
// Helpers
// ---------------------------------------------------------------------------
__device__ __forceinline__ uint32_t smem_u32(const void* p) {
    uint32_t a;
    asm("{ .reg .u64 t; cvta.to.shared.u64 t, %1; cvt.u32.u64 %0, t; }" : "=r"(a) : "l"(p));
    return a;
}
__device__ __forceinline__ void cp16(uint32_t dst, const void* src) {
    asm volatile("cp.async.cg.shared.global [%0], [%1], 16;" :: "r"(dst), "l"(src));
}
#define CP_COMMIT() asm volatile("cp.async.commit_group;" ::: "memory")
#define CP_WAIT2()  asm volatile("cp.async.wait_group 2;" ::: "memory")

__device__ __forceinline__ void ldm_x4(uint32_t a, uint32_t& r0, uint32_t& r1, uint32_t& r2, uint32_t& r3) {
    asm volatile("ldmatrix.sync.aligned.m8n8.x4.shared.b16 {%0,%1,%2,%3}, [%4];"
                 : "=r"(r0), "=r"(r1), "=r"(r2), "=r"(r3) : "r"(a));
}
__device__ __forceinline__ void ldm_x4_t(uint32_t a, uint32_t& r0, uint32_t& r1, uint32_t& r2, uint32_t& r3) {
    asm volatile("ldmatrix.sync.aligned.m8n8.x4.trans.shared.b16 {%0,%1,%2,%3}, [%4];"
                 : "=r"(r0), "=r"(r1), "=r"(r2), "=r"(r3) : "r"(a));
}
__device__ __forceinline__ void mma16816(float* d, const uint32_t* a, const uint32_t* b) {
    asm volatile("mma.sync.aligned.m16n8k16.row.col.f32.f16.f16.f32 "
                 "{%0,%1,%2,%3}, {%4,%5,%6,%7}, {%8,%9}, {%0,%1,%2,%3};"
                 : "+f"(d[0]), "+f"(d[1]), "+f"(d[2]), "+f"(d[3])
                 : "r"(a[0]), "r"(a[1]), "r"(a[2]), "r"(a[3]), "r"(b[0]), "r"(b[1]));
}

// ---------------------------------------------------------------------------
// fp16 GEMM via mma.sync:  C = alpha*(A @ B^T) [+bias] [+resid]
//   A: [M,K] fp16 K-major, row stride K, batch stride sA
//   B (BTRANS=0): [N,K] fp16 K-major (row stride K)
//   B (BTRANS=1): [K,N] fp16 N-major (row stride N)  -- e.g. natural V [S][D]
// CTA tile 128x256, K-chunk 64, 3-stage cp.async pipeline, 256 threads.
// Warp grid 2(M) x 4(N): warp tile 64x64.
// ---------------------------------------------------------------------------
#define BM 128
#define BN 256
#define BK 64
#define ROWB_A 144                       // 128B data + 16B pad
#define ROWB_BS 144                      // standard B rows (256 rows x 128B)
#define ROWB_BT 528                      // trans B rows (64 rows x 512B + 16B pad)
#define A_ARR (128 * ROWB_A)             // 18432

template<bool BIAS, bool RESID, bool WF32, bool WH, bool BTRANS>
__global__ __launch_bounds__(256, 1)
void gemm_mma(const __half* __restrict__ A_g, const __half* __restrict__ B_g,
              const float* __restrict__ bias, const float* __restrict__ resid,
              float* __restrict__ Cf, __half* __restrict__ Ch,
              int M, int N, int K, float alpha,
              long long sA, long long sB, long long sC)
{
    constexpr int B_ARR   = BTRANS ? (BK * ROWB_BT) : (256 * ROWB_BS);
    constexpr int OFF_B   = A_ARR;
    constexpr int STAGE   = A_ARR + B_ARR;

    extern __shared__ __align__(128) char smem[];
    const uint32_t sb = smem_u32(smem);
    const int tid = threadIdx.x;
    const int wid = tid >> 5, lane = tid & 31;
    const int wm = wid & 1, wn = wid >> 1;
    const int m0 = blockIdx.y * BM;
    const int n0 = blockIdx.x * BN;
    const long long zA = (long long)blockIdx.z * sA;
    const long long zB = (long long)blockIdx.z * sB;
    const long long zC = (long long)blockIdx.z * sC;

    // A loader: 8 x 16B segs per 128B row
    const int lr = tid >> 3;              // 0..31
    const int lcb = (tid & 7) * 16;
    const int lce = (tid & 7) * 8;

    float acc[4][8][4];
    #pragma unroll
    for (int i = 0; i < 4; i++)
        #pragma unroll
        for (int j = 0; j < 8; j++)
            #pragma unroll
            for (int t = 0; t < 4; t++) acc[i][j][t] = 0.0f;

    // fragment offsets
    const int arow = (lane & 7) + ((lane >> 3) & 1) * 8;
    const int kseg_a = lane >> 4;
    int aoff[4];
    #pragma unroll
    for (int mt = 0; mt < 4; mt++) aoff[mt] = (wm * 64 + mt * 16 + arow) * ROWB_A + kseg_a * 16;

    int boff[4];
    if (BTRANS) {
        // stored [k rows][n cols]: lanes 0-7 k0-7, 8-15 k8-15, 16-23 k0-7(n+8), 24-31 k8-15(n+8)
        const int krow = (lane & 7) + ((lane >> 3) & 1) * 8;
        const int ncol8 = ((lane >> 4) & 1) * 8;
        #pragma unroll
        for (int p = 0; p < 4; p++)
            boff[p] = krow * ROWB_BT + (wn * 64 + p * 16 + ncol8) * 2;
    } else {
        const int brow = ((lane >> 4) << 3) + (lane & 7);
        const int kseg_b = (lane >> 3) & 1;
        #pragma unroll
        for (int p = 0; p < 4; p++)
            boff[p] = (wn * 64 + p * 16 + brow) * ROWB_BS + kseg_b * 16;
    }

    const int nc = K / BK;

    auto issue_loads = [&](int kc) {
        const uint32_t stu = sb + (kc % 3) * STAGE;
        const int kb = kc * BK;
        // A: 128 rows x 8 segs, 4 per thread
        #pragma unroll
        for (int i = 0; i < 4; i++) {
            const int r = lr + i * 32;
            const long long g = zA + (long long)(m0 + r) * K + kb + lce;
            cp16(stu + r * ROWB_A + lcb, A_g + g);
        }
        if (BTRANS) {
            // B: 64 rows (k) x 32 segs (512B), 8 per thread
            const int r0 = tid >> 5;              // 0..7
            const int cs = (tid & 31);            // seg in row
            #pragma unroll
            for (int i = 0; i < 8; i++) {
                const int r = r0 + i * 8;
                const long long g = zB + (long long)(kb + r) * N + n0 + cs * 8;
                cp16(stu + OFF_B + r * ROWB_BT + cs * 16, B_g + g);
            }
        } else {
            // B: 256 rows x 8 segs, 8 per thread
            #pragma unroll
            for (int i = 0; i < 8; i++) {
                const int r = lr + i * 32;
                const long long g = zB + (long long)(n0 + r) * K + kb + lce;
                cp16(stu + OFF_B + r * ROWB_BS + lcb, B_g + g);
            }
        }
    };

    issue_loads(0); CP_COMMIT();
    if (nc > 1) issue_loads(1);
    CP_COMMIT();

    for (int kc = 0; kc < nc; kc++) {
        __syncthreads();
        if (kc + 2 < nc) issue_loads(kc + 2);
        CP_COMMIT();
        CP_WAIT2();
        __syncthreads();

        const uint32_t stu = sb + (kc % 3) * STAGE;

        #pragma unroll
        for (int ks = 0; ks < 4; ks++) {
            uint32_t ah[4][4];
            #pragma unroll
            for (int mt = 0; mt < 4; mt++)
                ldm_x4(stu + aoff[mt] + ks * 32, ah[mt][0], ah[mt][1], ah[mt][2], ah[mt][3]);
            #pragma unroll
            for (int p = 0; p < 4; p++) {
                uint32_t b[2][2];
                if (BTRANS)
                    ldm_x4_t(stu + OFF_B + boff[p] + ks * 16 * ROWB_BT,
                             b[0][0], b[0][1], b[1][0], b[1][1]);
                else
                    ldm_x4(stu + OFF_B + boff[p] + ks * 32,
                           b[0][0], b[0][1], b[1][0], b[1][1]);
                #pragma unroll
                for (int mt = 0; mt < 4; mt++) {
                    mma16816(acc[mt][2 * p + 0], ah[mt], b[0]);
                    mma16816(acc[mt][2 * p + 1], ah[mt], b[1]);
                }
            }
        }
    }

    // ---- epilogue ----
    const int gr = lane >> 2, qc = (lane & 3) * 2;
    #pragma unroll
    for (int mt = 0; mt < 4; mt++) {
        #pragma unroll
        for (int half_ = 0; half_ < 2; half_++) {
            const int m = m0 + wm * 64 + mt * 16 + gr + half_ * 8;
            const long long crow = zC + (long long)m * N;
            #pragma unroll
            for (int nt = 0; nt < 8; nt++) {
                const int c = n0 + wn * 64 + nt * 8 + qc;
                float v0 = acc[mt][nt][half_ * 2 + 0] * alpha;
                float v1 = acc[mt][nt][half_ * 2 + 1] * alpha;
                if (BIAS)  { v0 += __ldg(&bias[c]); v1 += __ldg(&bias[c + 1]); }
                if (RESID) { v0 += resid[crow + c]; v1 += resid[crow + c + 1]; }
                if (WF32)  { *(float2*)(Cf + crow + c) = make_float2(v0, v1); }
                if (WH) {
                    __half2 hv; hv.x = __float2half_rn(v0); hv.y = __float2half_rn(v1);
                    *(__half2*)(Ch + crow + c) = hv;
                }
            }
        }
    }
}

#define SMEM_STD (3 * (A_ARR + 256 * ROWB_BS))   // 165888
#define SMEM_TRN (3 * (A_ARR + BK * ROWB_BT))    // 156672

// ---------------------------------------------------------------------------
// GELU (exact erf) -> fp16, 8 elems/thread vectorized
// ---------------------------------------------------------------------------
__global__ __launch_bounds__(256)
void gelu_kernel(const float* __restrict__ in, __half* __restrict__ o, int n)
{
    int i = (blockIdx.x * blockDim.x + threadIdx.x) * 8;
    if (i < n) {
        float4 a = *(const float4*)(in + i);
        float4 b = *(const float4*)(in + i + 4);
        float r[8] = {a.x, a.y, a.z, a.w, b.x, b.y, b.z, b.w};
        __half h[8];
        #pragma unroll
        for (int j = 0; j < 8; j++) {
            float t = r[j];
            h[j] = __float2half_rn(0.5f * t * (1.0f + erff(t * 0.70710678118654752f)));
        }
        *(uint4*)(o + i) = *(uint4*)h;
    }
}

// ---------------------------------------------------------------------------
// Weight transpose:  W[K][N] fp32 -> Wt [N][K] fp16
// ---------------------------------------------------------------------------
__global__ __launch_bounds__(256)
void wt_kernel(const float* __restrict__ W, __half* __restrict__ T)
{
    __shared__ float t[32][33];
    const int n0 = blockIdx.x * 32, k0 = blockIdx.y * 32;
    const int tx = threadIdx.x, ty = threadIdx.y;
    #pragma unroll
    for (int i = 0; i < 4; i++)
        t[ty + i * 8][tx] = W[(k0 + ty + i * 8) * DM + n0 + tx];
    __syncthreads();
    #pragma unroll
    for (int i = 0; i < 4; i++)
        T[(n0 + ty + i * 8) * DM + k0 + tx] = __float2half_rn(t[tx][ty + i * 8]);
}

// ---------------------------------------------------------------------------
// Softmax over fp16 scores -> fp16 probs. 256 thr / row of 2048, uint4 I/O.
// ---------------------------------------------------------------------------
__global__ __launch_bounds__(256)
void softmax_kernel(const __half* __restrict__ S, __half* __restrict__ P)
{
    const long long row = (long long)blockIdx.x * SEQ;
    const int tid = threadIdx.x;
    __shared__ float red[8];

    uint4 pk = *(const uint4*)(S + row + tid * 8);
    __half h[8];
    *(uint4*)h = pk;
    float v[8];
    #pragma unroll
    for (int i = 0; i < 8; i++) v[i] = __half2float(h[i]);

    float mx = v[0];
    #pragma unroll
    for (int i = 1; i < 8; i++) mx = fmaxf(mx, v[i]);
    #pragma unroll
    for (int o = 16; o > 0; o >>= 1) mx = fmaxf(mx, __shfl_xor_sync(0xffffffffu, mx, o));
    if ((tid & 31) == 0) red[tid >> 5] = mx;
    __syncthreads();
    float rmax = red[0];
    #pragma unroll
    for (int i = 1; i < 8; i++) rmax = fmaxf(rmax, red[i]);
    __syncthreads();

    float sum = 0.0f;
    #pragma unroll
    for (int i = 0; i < 8; i++) { v[i] = __expf(v[i] - rmax); sum += v[i]; }
    #pragma unroll
    for (int o = 16; o > 0; o >>= 1) sum += __shfl_xor_sync(0xffffffffu, sum, o);
    if ((tid & 31) == 0) red[tid >> 5] = sum;
    __syncthreads();
    float rsum = 0.0f;
    #pragma unroll
    for (int i = 0; i < 8; i++) rsum += red[i];
    const float inv = 1.0f / rsum;

    #pragma unroll
    for (int i = 0; i < 8; i++) h[i] = __float2half_rn(v[i] * inv);
    *(uint4*)(P + row + tid * 8) = *(uint4*)h;
}

// ---------------------------------------------------------------------------
// Launch
// ---------------------------------------------------------------------------
extern "C" void kernel_launch(void* const* d_in, const int* in_sizes, int n_in,
                              void* d_out, int out_size)
{
    const float* tokens = (const float*)d_in[0];
    const float* Wq = (const float*)d_in[1];
    const float* bq = (const float*)d_in[2];
    const float* Wk = (const float*)d_in[3];
    const float* bk = (const float*)d_in[4];
    const float* Wv = (const float*)d_in[5];
    const float* bv = (const float*)d_in[6];
    const float* Wo = (const float*)d_in[7];
    const float* bo = (const float*)d_in[8];
    float* out = (float*)d_out;

    __half *x, *wt, *q, *k, *v, *s, *pp, *m;
    cudaGetSymbolAddress((void**)&x, g_x);
    cudaGetSymbolAddress((void**)&wt, g_wt);
    cudaGetSymbolAddress((void**)&q, g_q);
    cudaGetSymbolAddress((void**)&k, g_k);
    cudaGetSymbolAddress((void**)&v, g_v);
    cudaGetSymbolAddress((void**)&s, g_s);
    cudaGetSymbolAddress((void**)&pp, g_p);
    cudaGetSymbolAddress((void**)&m, g_m);

    // raise smem cap on every launched instantiation
    cudaFuncSetAttribute(gemm_mma<true,  false, false, true,  false>, cudaFuncAttributeMaxDynamicSharedMemorySize, SMEM_STD);
    cudaFuncSetAttribute(gemm_mma<false, false, false, true,  false>, cudaFuncAttributeMaxDynamicSharedMemorySize, SMEM_STD);
    cudaFuncSetAttribute(gemm_mma<false, false, false, true,  true >, cudaFuncAttributeMaxDynamicSharedMemorySize, SMEM_TRN);
    cudaFuncSetAttribute(gemm_mma<true,  true,  true,  false, false>, cudaFuncAttributeMaxDynamicSharedMemorySize, SMEM_STD);

    const int nTok = BS * DM;
    const float scale = 1.0f / 32.0f;

    // 1) gelu -> fp16 (vectorized, 8/thread)
    gelu_kernel<<<nTok / 8 / 256, 256>>>(tokens, x, nTok);

    // 2) weight transposes -> fp16
    {
        dim3 grid(32, 32), blk(32, 8);
        wt_kernel<<<grid, blk>>>(Wq, wt + 0 * DM * DM);
        wt_kernel<<<grid, blk>>>(Wk, wt + 1 * DM * DM);
        wt_kernel<<<grid, blk>>>(Wv, wt + 2 * DM * DM);
        wt_kernel<<<grid, blk>>>(Wo, wt + 3 * DM * DM);
    }

    // 3) Q, K, V projections -> fp16
    {
        dim3 grid(DM / BN, BS / BM, 1);
        gemm_mma<true, false, false, true, false><<<grid, 256, SMEM_STD>>>(
            x, wt + 0 * DM * DM, bq, nullptr, nullptr, q, BS, DM, DM, 1.0f, 0, 0, 0);
        gemm_mma<true, false, false, true, false><<<grid, 256, SMEM_STD>>>(
            x, wt + 1 * DM * DM, bk, nullptr, nullptr, k, BS, DM, DM, 1.0f, 0, 0, 0);
        gemm_mma<true, false, false, true, false><<<grid, 256, SMEM_STD>>>(
            x, wt + 2 * DM * DM, bv, nullptr, nullptr, v, BS, DM, DM, 1.0f, 0, 0, 0);
    }

    // 4) scores = scale * Q @ K^T (batched) -> fp16
    {
        dim3 grid(SEQ / BN, SEQ / BM, BATCH);
        gemm_mma<false, false, false, true, false><<<grid, 256, SMEM_STD>>>(
            q, k, nullptr, nullptr, nullptr, s, SEQ, SEQ, DM, scale,
            (long long)SEQ * DM, (long long)SEQ * DM, (long long)SEQ * SEQ);
    }

    // 5) softmax -> fp16 probs
    softmax_kernel<<<BS, 256>>>(s, pp);

    // 6) mixed = attn @ V (batched, V natural layout via trans-ldmatrix) -> fp16
    {
        dim3 grid(DM / BN, SEQ / BM, BATCH);
        gemm_mma<false, false, false, true, true><<<grid, 256, SMEM_TRN>>>(
            pp, v, nullptr, nullptr, nullptr, m, SEQ, DM, SEQ, 1.0f,
            (long long)SEQ * SEQ, (long long)SEQ * DM, (long long)SEQ * DM);
    }

    // 7) out = mixed @ Wo^T + bo + tokens -> fp32
    {
        dim3 grid(DM / BN, BS / BM, 1);
        gemm_mma<true, true, true, false, false><<<grid, 256, SMEM_STD>>>(
            m, wt + 3 * DM * DM, bo, tokens, out, nullptr, BS, DM, DM, 1.0f, 0, 0, 0);
    }
}

// round 11
// speedup vs baseline: 6.8736x; 1.0258x over previous
#include <cuda_runtime.h>
#include <cuda_fp16.h>
#include <math.h>
#include <stdint.h>

#define BATCH 4
#define SEQ   2048
#define DM    1024
#define BS    (BATCH * SEQ)

// ---------------------------------------------------------------------------
// Scratch (allocation-free: __device__ globals)
// ---------------------------------------------------------------------------
__device__ __half g_x[BS * DM];                 // gelu(tokens)
__device__ __half g_wt[4][DM * DM];             // transposed weights [N][K]
__device__ __half g_q[BS * DM];
__device__ __half g_k[BS * DM];
__device__ __half g_v[BS * DM];
__device__ __half g_s[BATCH * SEQ * SEQ];       // scores fp16 (32MB)
__device__ __half g_p[BATCH * SEQ * SEQ];       // probs fp16
__device__ __half g_m[BS * DM];                 // mixed fp16

// ---------------------------------------------------------------------------
// Helpers
// ---------------------------------------------------------------------------
__device__ __forceinline__ uint32_t smem_u32(const void* p) {
    uint32_t a;
    asm("{ .reg .u64 t; cvta.to.shared.u64 t, %1; cvt.u32.u64 %0, t; }" : "=r"(a) : "l"(p));
    return a;
}
__device__ __forceinline__ void cp16(uint32_t dst, const void* src) {
    asm volatile("cp.async.cg.shared.global [%0], [%1], 16;" :: "r"(dst), "l"(src));
}
#define CP_COMMIT()   asm volatile("cp.async.commit_group;" ::: "memory")
#define CP_WAIT_ALL() asm volatile("cp.async.wait_group 0;" ::: "memory")

__device__ __forceinline__ void ldm_x4(uint32_t a, uint32_t& r0, uint32_t& r1, uint32_t& r2, uint32_t& r3) {
    asm volatile("ldmatrix.sync.aligned.m8n8.x4.shared.b16 {%0,%1,%2,%3}, [%4];"
                 : "=r"(r0), "=r"(r1), "=r"(r2), "=r"(r3) : "r"(a));
}
__device__ __forceinline__ void ldm_x4_t(uint32_t a, uint32_t& r0, uint32_t& r1, uint32_t& r2, uint32_t& r3) {
    asm volatile("ldmatrix.sync.aligned.m8n8.x4.trans.shared.b16 {%0,%1,%2,%3}, [%4];"
                 : "=r"(r0), "=r"(r1), "=r"(r2), "=r"(r3) : "r"(a));
}
__device__ __forceinline__ void mma16816(float* d, const uint32_t* a, const uint32_t* b) {
    asm volatile("mma.sync.aligned.m16n8k16.row.col.f32.f16.f16.f32 "
                 "{%0,%1,%2,%3}, {%4,%5,%6,%7}, {%8,%9}, {%0,%1,%2,%3};"
                 : "+f"(d[0]), "+f"(d[1]), "+f"(d[2]), "+f"(d[3])
                 : "r"(a[0]), "r"(a[1]), "r"(a[2]), "r"(a[3]), "r"(b[0]), "r"(b[1]));
}

// ---------------------------------------------------------------------------
// fp16 GEMM via mma.sync:  C = alpha*(A @ B^T) [+bias] [+resid]
//   A: [M,K] fp16 K-major, batch stride sA
//   B (BTRANS=0): [N,K] fp16 K-major
//   B (BTRANS=1): [K,N] fp16 N-major (natural V [S][D])
// CTA tile 128x256, K-chunk 128, 2-stage cp.async pipeline, 1 barrier/chunk.
// Warp grid 2(M) x 4(N): warp tile 64x64.
// Row pitches 272B / 528B: stride mod 32 banks = 4 -> conflict-free ldmatrix.
// ---------------------------------------------------------------------------
#define BM 128
#define BN 256
#define BK 128
#define ROWB_A 272                       // 256B data + 16B pad
#define ROWB_BS 272
#define ROWB_BT 528                      // 512B data + 16B pad
#define A_ARR (128 * ROWB_A)             // 34816

template<bool BIAS, bool RESID, bool WF32, bool WH, bool BTRANS>
__global__ __launch_bounds__(256, 1)
void gemm_mma(const __half* __restrict__ A_g, const __half* __restrict__ B_g,
              const float* __restrict__ bias, const float* __restrict__ resid,
              float* __restrict__ Cf, __half* __restrict__ Ch,
              int M, int N, int K, float alpha,
              long long sA, long long sB, long long sC)
{
    constexpr int B_ARR = BTRANS ? (BK * ROWB_BT) : (256 * ROWB_BS);
    constexpr int OFF_B = A_ARR;
    constexpr int STAGE = A_ARR + B_ARR;

    extern __shared__ __align__(128) char smem[];
    const uint32_t sb = smem_u32(smem);
    const int tid = threadIdx.x;
    const int wid = tid >> 5, lane = tid & 31;
    const int wm = wid & 1, wn = wid >> 1;
    const int m0 = blockIdx.y * BM;
    const int n0 = blockIdx.x * BN;
    const long long zA = (long long)blockIdx.z * sA;
    const long long zB = (long long)blockIdx.z * sB;
    const long long zC = (long long)blockIdx.z * sC;

    // loader mapping: 16 x 16B segs per 256B row
    const int lr  = tid >> 4;             // 0..15
    const int seg = tid & 15;
    const int lcb = seg * 16;             // byte offset in row
    const int lce = seg * 8;              // element offset in row

    float acc[4][8][4];
    #pragma unroll
    for (int i = 0; i < 4; i++)
        #pragma unroll
        for (int j = 0; j < 8; j++)
            #pragma unroll
            for (int t = 0; t < 4; t++) acc[i][j][t] = 0.0f;

    // fragment offsets
    const int arow = (lane & 7) + ((lane >> 3) & 1) * 8;
    const int kseg_a = lane >> 4;
    int aoff[4];
    #pragma unroll
    for (int mt = 0; mt < 4; mt++) aoff[mt] = (wm * 64 + mt * 16 + arow) * ROWB_A + kseg_a * 16;

    int boff[4];
    if (BTRANS) {
        const int krow = (lane & 7) + ((lane >> 3) & 1) * 8;
        const int ncol8 = ((lane >> 4) & 1) * 8;
        #pragma unroll
        for (int p = 0; p < 4; p++)
            boff[p] = krow * ROWB_BT + (wn * 64 + p * 16 + ncol8) * 2;
    } else {
        const int brow = ((lane >> 4) << 3) + (lane & 7);
        const int kseg_b = (lane >> 3) & 1;
        #pragma unroll
        for (int p = 0; p < 4; p++)
            boff[p] = (wn * 64 + p * 16 + brow) * ROWB_BS + kseg_b * 16;
    }

    const int nc = K / BK;

    auto issue_loads = [&](int kc) {
        const uint32_t stu = sb + (kc & 1) * STAGE;
        const int kb = kc * BK;
        // A: 128 rows x 16 segs = 2048 segs, 8 per thread
        #pragma unroll
        for (int i = 0; i < 8; i++) {
            const int r = lr + i * 16;
            const long long g = zA + (long long)(m0 + r) * K + kb + lce;
            cp16(stu + r * ROWB_A + lcb, A_g + g);
        }
        if (BTRANS) {
            // B: 128 k-rows x 32 segs (512B) = 4096 segs, 16 per thread
            const int r0 = tid >> 5;          // 0..7
            const int cs = tid & 31;
            #pragma unroll
            for (int i = 0; i < 16; i++) {
                const int r = r0 + i * 8;
                const long long g = zB + (long long)(kb + r) * N + n0 + cs * 8;
                cp16(stu + OFF_B + r * ROWB_BT + cs * 16, B_g + g);
            }
        } else {
            // B: 256 rows x 16 segs = 4096 segs, 16 per thread
            #pragma unroll
            for (int i = 0; i < 16; i++) {
                const int r = lr + i * 16;
                const long long g = zB + (long long)(n0 + r) * K + kb + lce;
                cp16(stu + OFF_B + r * ROWB_BS + lcb, B_g + g);
            }
        }
    };

    // prologue: stage 0 in flight
    issue_loads(0); CP_COMMIT();

    for (int kc = 0; kc < nc; kc++) {
        CP_WAIT_ALL();        // exactly one group in flight: chunk kc
        __syncthreads();      // data visible + all warps done computing kc-1
        if (kc + 1 < nc) { issue_loads(kc + 1); CP_COMMIT(); }

        const uint32_t stu = sb + (kc & 1) * STAGE;

        #pragma unroll
        for (int ks = 0; ks < 8; ks++) {
            uint32_t ah[4][4];
            #pragma unroll
            for (int mt = 0; mt < 4; mt++)
                ldm_x4(stu + aoff[mt] + ks * 32, ah[mt][0], ah[mt][1], ah[mt][2], ah[mt][3]);
            #pragma unroll
            for (int p = 0; p < 4; p++) {
                uint32_t b[2][2];
                if (BTRANS)
                    ldm_x4_t(stu + OFF_B + boff[p] + ks * 16 * ROWB_BT,
                             b[0][0], b[0][1], b[1][0], b[1][1]);
                else
                    ldm_x4(stu + OFF_B + boff[p] + ks * 32,
                           b[0][0], b[0][1], b[1][0], b[1][1]);
                #pragma unroll
                for (int mt = 0; mt < 4; mt++) {
                    mma16816(acc[mt][2 * p + 0], ah[mt], b[0]);
                    mma16816(acc[mt][2 * p + 1], ah[mt], b[1]);
                }
            }
        }
    }

    // ---- epilogue ----
    const int gr = lane >> 2, qc = (lane & 3) * 2;
    #pragma unroll
    for (int mt = 0; mt < 4; mt++) {
        #pragma unroll
        for (int half_ = 0; half_ < 2; half_++) {
            const int m = m0 + wm * 64 + mt * 16 + gr + half_ * 8;
            const long long crow = zC + (long long)m * N;
            #pragma unroll
            for (int nt = 0; nt < 8; nt++) {
                const int c = n0 + wn * 64 + nt * 8 + qc;
                float v0 = acc[mt][nt][half_ * 2 + 0] * alpha;
                float v1 = acc[mt][nt][half_ * 2 + 1] * alpha;
                if (BIAS)  { v0 += __ldg(&bias[c]); v1 += __ldg(&bias[c + 1]); }
                if (RESID) { v0 += resid[crow + c]; v1 += resid[crow + c + 1]; }
                if (WF32)  { *(float2*)(Cf + crow + c) = make_float2(v0, v1); }
                if (WH) {
                    __half2 hv; hv.x = __float2half_rn(v0); hv.y = __float2half_rn(v1);
                    *(__half2*)(Ch + crow + c) = hv;
                }
            }
        }
    }
}

#define SMEM_STD (2 * (A_ARR + 256 * ROWB_BS))   // 208896
#define SMEM_TRN (2 * (A_ARR + BK * ROWB_BT))    // 204800

// ---------------------------------------------------------------------------
// GELU (exact erf) -> fp16, 8 elems/thread vectorized
// ---------------------------------------------------------------------------
__global__ __launch_bounds__(256)
void gelu_kernel(const float* __restrict__ in, __half* __restrict__ o, int n)
{
    int i = (blockIdx.x * blockDim.x + threadIdx.x) * 8;
    if (i < n) {
        float4 a = *(const float4*)(in + i);
        float4 b = *(const float4*)(in + i + 4);
        float r[8] = {a.x, a.y, a.z, a.w, b.x, b.y, b.z, b.w};
        __half h[8];
        #pragma unroll
        for (int j = 0; j < 8; j++) {
            float t = r[j];
            h[j] = __float2half_rn(0.5f * t * (1.0f + erff(t * 0.70710678118654752f)));
        }
        *(uint4*)(o + i) = *(uint4*)h;
    }
}

// ---------------------------------------------------------------------------
// Weight transpose:  W[K][N] fp32 -> Wt [N][K] fp16
// ---------------------------------------------------------------------------
__global__ __launch_bounds__(256)
void wt_kernel(const float* __restrict__ W, __half* __restrict__ T)
{
    __shared__ float t[32][33];
    const int n0 = blockIdx.x * 32, k0 = blockIdx.y * 32;
    const int tx = threadIdx.x, ty = threadIdx.y;
    #pragma unroll
    for (int i = 0; i < 4; i++)
        t[ty + i * 8][tx] = W[(k0 + ty + i * 8) * DM + n0 + tx];
    __syncthreads();
    #pragma unroll
    for (int i = 0; i < 4; i++)
        T[(n0 + ty + i * 8) * DM + k0 + tx] = __float2half_rn(t[tx][ty + i * 8]);
}

// ---------------------------------------------------------------------------
// Softmax over fp16 scores -> fp16 probs. 256 thr / row of 2048, uint4 I/O.
// ---------------------------------------------------------------------------
__global__ __launch_bounds__(256)
void softmax_kernel(const __half* __restrict__ S, __half* __restrict__ P)
{
    const long long row = (long long)blockIdx.x * SEQ;
    const int tid = threadIdx.x;
    __shared__ float red[8];

    uint4 pk = *(const uint4*)(S + row + tid * 8);
    __half h[8];
    *(uint4*)h = pk;
    float v[8];
    #pragma unroll
    for (int i = 0; i < 8; i++) v[i] = __half2float(h[i]);

    float mx = v[0];
    #pragma unroll
    for (int i = 1; i < 8; i++) mx = fmaxf(mx, v[i]);
    #pragma unroll
    for (int o = 16; o > 0; o >>= 1) mx = fmaxf(mx, __shfl_xor_sync(0xffffffffu, mx, o));
    if ((tid & 31) == 0) red[tid >> 5] = mx;
    __syncthreads();
    float rmax = red[0];
    #pragma unroll
    for (int i = 1; i < 8; i++) rmax = fmaxf(rmax, red[i]);
    __syncthreads();

    float sum = 0.0f;
    #pragma unroll
    for (int i = 0; i < 8; i++) { v[i] = __expf(v[i] - rmax); sum += v[i]; }
    #pragma unroll
    for (int o = 16; o > 0; o >>= 1) sum += __shfl_xor_sync(0xffffffffu, sum, o);
    if ((tid & 31) == 0) red[tid >> 5] = sum;
    __syncthreads();
    float rsum = 0.0f;
    #pragma unroll
    for (int i = 0; i < 8; i++) rsum += red[i];
    const float inv = 1.0f / rsum;

    #pragma unroll
    for (int i = 0; i < 8; i++) h[i] = __float2half_rn(v[i] * inv);
    *(uint4*)(P + row + tid * 8) = *(uint4*)h;
}

// ---------------------------------------------------------------------------
// Launch
// ---------------------------------------------------------------------------
extern "C" void kernel_launch(void* const* d_in, const int* in_sizes, int n_in,
                              void* d_out, int out_size)
{
    const float* tokens = (const float*)d_in[0];
    const float* Wq = (const float*)d_in[1];
    const float* bq = (const float*)d_in[2];
    const float* Wk = (const float*)d_in[3];
    const float* bk = (const float*)d_in[4];
    const float* Wv = (const float*)d_in[5];
    const float* bv = (const float*)d_in[6];
    const float* Wo = (const float*)d_in[7];
    const float* bo = (const float*)d_in[8];
    float* out = (float*)d_out;

    __half *x, *wt, *q, *k, *v, *s, *pp, *m;
    cudaGetSymbolAddress((void**)&x, g_x);
    cudaGetSymbolAddress((void**)&wt, g_wt);
    cudaGetSymbolAddress((void**)&q, g_q);
    cudaGetSymbolAddress((void**)&k, g_k);
    cudaGetSymbolAddress((void**)&v, g_v);
    cudaGetSymbolAddress((void**)&s, g_s);
    cudaGetSymbolAddress((void**)&pp, g_p);
    cudaGetSymbolAddress((void**)&m, g_m);

    // raise smem cap on every launched instantiation
    cudaFuncSetAttribute(gemm_mma<true,  false, false, true,  false>, cudaFuncAttributeMaxDynamicSharedMemorySize, SMEM_STD);
    cudaFuncSetAttribute(gemm_mma<false, false, false, true,  false>, cudaFuncAttributeMaxDynamicSharedMemorySize, SMEM_STD);
    cudaFuncSetAttribute(gemm_mma<false, false, false, true,  true >, cudaFuncAttributeMaxDynamicSharedMemorySize, SMEM_TRN);
    cudaFuncSetAttribute(gemm_mma<true,  true,  true,  false, false>, cudaFuncAttributeMaxDynamicSharedMemorySize, SMEM_STD);

    const int nTok = BS * DM;
    const float scale = 1.0f / 32.0f;

    // 1) gelu -> fp16 (vectorized, 8/thread)
    gelu_kernel<<<nTok / 8 / 256, 256>>>(tokens, x, nTok);

    // 2) weight transposes -> fp16
    {
        dim3 grid(32, 32), blk(32, 8);
        wt_kernel<<<grid, blk>>>(Wq, wt + 0 * DM * DM);
        wt_kernel<<<grid, blk>>>(Wk, wt + 1 * DM * DM);
        wt_kernel<<<grid, blk>>>(Wv, wt + 2 * DM * DM);
        wt_kernel<<<grid, blk>>>(Wo, wt + 3 * DM * DM);
    }

    // 3) Q, K, V projections -> fp16
    {
        dim3 grid(DM / BN, BS / BM, 1);
        gemm_mma<true, false, false, true, false><<<grid, 256, SMEM_STD>>>(
            x, wt + 0 * DM * DM, bq, nullptr, nullptr, q, BS, DM, DM, 1.0f, 0, 0, 0);
        gemm_mma<true, false, false, true, false><<<grid, 256, SMEM_STD>>>(
            x, wt + 1 * DM * DM, bk, nullptr, nullptr, k, BS, DM, DM, 1.0f, 0, 0, 0);
        gemm_mma<true, false, false, true, false><<<grid, 256, SMEM_STD>>>(
            x, wt + 2 * DM * DM, bv, nullptr, nullptr, v, BS, DM, DM, 1.0f, 0, 0, 0);
    }

    // 4) scores = scale * Q @ K^T (batched) -> fp16
    {
        dim3 grid(SEQ / BN, SEQ / BM, BATCH);
        gemm_mma<false, false, false, true, false><<<grid, 256, SMEM_STD>>>(
            q, k, nullptr, nullptr, nullptr, s, SEQ, SEQ, DM, scale,
            (long long)SEQ * DM, (long long)SEQ * DM, (long long)SEQ * SEQ);
    }

    // 5) softmax -> fp16 probs
    softmax_kernel<<<BS, 256>>>(s, pp);

    // 6) mixed = attn @ V (batched, V natural layout via trans-ldmatrix) -> fp16
    {
        dim3 grid(DM / BN, SEQ / BM, BATCH);
        gemm_mma<false, false, false, true, true><<<grid, 256, SMEM_TRN>>>(
            pp, v, nullptr, nullptr, nullptr, m, SEQ, DM, SEQ, 1.0f,
            (long long)SEQ * SEQ, (long long)SEQ * DM, (long long)SEQ * DM);
    }

    // 7) out = mixed @ Wo^T + bo + tokens -> fp32
    {
        dim3 grid(DM / BN, BS / BM, 1);
        gemm_mma<true, true, true, false, false><<<grid, 256, SMEM_STD>>>(
            m, wt + 3 * DM * DM, bo, tokens, out, nullptr, BS, DM, DM, 1.0f, 0, 0, 0);
    }
}

// round 12
// speedup vs baseline: 6.9493x; 1.0110x over previous
#include <cuda_runtime.h>
#include <cuda_fp16.h>
#include <math.h>
#include <stdint.h>

#define BATCH 4
#define SEQ   2048
#define DM    1024
#define BS    (BATCH * SEQ)

// ---------------------------------------------------------------------------
// Scratch (allocation-free: __device__ globals)
// ---------------------------------------------------------------------------
__device__ __half g_x[BS * DM];                 // gelu(tokens)
__device__ __half g_wt[4][DM * DM];             // transposed weights [N][K]
__device__ __half g_q[BS * DM];
__device__ __half g_k[BS * DM];
__device__ __half g_v[BS * DM];
__device__ __half g_s[BATCH * SEQ * SEQ];       // scores fp16 (32MB)
__device__ __half g_p[BATCH * SEQ * SEQ];       // probs fp16
__device__ __half g_m[BS * DM];                 // mixed fp16

// ---------------------------------------------------------------------------
// Helpers
// ---------------------------------------------------------------------------
__device__ __forceinline__ uint32_t smem_u32(const void* p) {
    uint32_t a;
    asm("{ .reg .u64 t; cvta.to.shared.u64 t, %1; cvt.u32.u64 %0, t; }" : "=r"(a) : "l"(p));
    return a;
}
__device__ __forceinline__ void cp16(uint32_t dst, const void* src) {
    asm volatile("cp.async.cg.shared.global [%0], [%1], 16;" :: "r"(dst), "l"(src));
}
#define CP_COMMIT()   asm volatile("cp.async.commit_group;" ::: "memory")
#define CP_WAIT_ALL() asm volatile("cp.async.wait_group 0;" ::: "memory")

__device__ __forceinline__ void ldm_x4(uint32_t a, uint32_t& r0, uint32_t& r1, uint32_t& r2, uint32_t& r3) {
    asm volatile("ldmatrix.sync.aligned.m8n8.x4.shared.b16 {%0,%1,%2,%3}, [%4];"
                 : "=r"(r0), "=r"(r1), "=r"(r2), "=r"(r3) : "r"(a));
}
__device__ __forceinline__ void ldm_x4_t(uint32_t a, uint32_t& r0, uint32_t& r1, uint32_t& r2, uint32_t& r3) {
    asm volatile("ldmatrix.sync.aligned.m8n8.x4.trans.shared.b16 {%0,%1,%2,%3}, [%4];"
                 : "=r"(r0), "=r"(r1), "=r"(r2), "=r"(r3) : "r"(a));
}
__device__ __forceinline__ void mma16816(float* d, const uint32_t* a, const uint32_t* b) {
    asm volatile("mma.sync.aligned.m16n8k16.row.col.f32.f16.f16.f32 "
                 "{%0,%1,%2,%3}, {%4,%5,%6,%7}, {%8,%9}, {%0,%1,%2,%3};"
                 : "+f"(d[0]), "+f"(d[1]), "+f"(d[2]), "+f"(d[3])
                 : "r"(a[0]), "r"(a[1]), "r"(a[2]), "r"(a[3]), "r"(b[0]), "r"(b[1]));
}

// ---------------------------------------------------------------------------
// fp16 GEMM via mma.sync:  C = alpha*(A @ B^T) [+bias] [+resid]
//   A: [M,K] fp16 K-major, batch stride sA
//   B (BTRANS=0): [N,K] fp16 K-major
//   B (BTRANS=1): [K,N] fp16 N-major (natural V [S][D])
// CTA tile 128x256, K-chunk 128, 2-stage cp.async pipeline, 1 barrier/chunk.
// Warp grid 2(M) x 4(N): warp tile 64x64.
// Register-double-buffered fragments: ks+1 frags prefetched under ks MMAs.
// ---------------------------------------------------------------------------
#define BM 128
#define BN 256
#define BK 128
#define ROWB_A 272                       // 256B data + 16B pad
#define ROWB_BS 272
#define ROWB_BT 528                      // 512B data + 16B pad
#define A_ARR (128 * ROWB_A)             // 34816

template<bool BIAS, bool RESID, bool WF32, bool WH, bool BTRANS>
__global__ __launch_bounds__(256, 1)
void gemm_mma(const __half* __restrict__ A_g, const __half* __restrict__ B_g,
              const float* __restrict__ bias, const float* __restrict__ resid,
              float* __restrict__ Cf, __half* __restrict__ Ch,
              int M, int N, int K, float alpha,
              long long sA, long long sB, long long sC)
{
    constexpr int B_ARR = BTRANS ? (BK * ROWB_BT) : (256 * ROWB_BS);
    constexpr int OFF_B = A_ARR;
    constexpr int STAGE = A_ARR + B_ARR;

    extern __shared__ __align__(128) char smem[];
    const uint32_t sb = smem_u32(smem);
    const int tid = threadIdx.x;
    const int wid = tid >> 5, lane = tid & 31;
    const int wm = wid & 1, wn = wid >> 1;
    const int m0 = blockIdx.y * BM;
    const int n0 = blockIdx.x * BN;
    const long long zA = (long long)blockIdx.z * sA;
    const long long zB = (long long)blockIdx.z * sB;
    const long long zC = (long long)blockIdx.z * sC;

    // loader mapping: 16 x 16B segs per 256B row
    const int lr  = tid >> 4;
    const int seg = tid & 15;
    const int lcb = seg * 16;
    const int lce = seg * 8;

    float acc[4][8][4];
    #pragma unroll
    for (int i = 0; i < 4; i++)
        #pragma unroll
        for (int j = 0; j < 8; j++)
            #pragma unroll
            for (int t = 0; t < 4; t++) acc[i][j][t] = 0.0f;

    // fragment offsets
    const int arow = (lane & 7) + ((lane >> 3) & 1) * 8;
    const int kseg_a = lane >> 4;
    int aoff[4];
    #pragma unroll
    for (int mt = 0; mt < 4; mt++) aoff[mt] = (wm * 64 + mt * 16 + arow) * ROWB_A + kseg_a * 16;

    int boff[4];
    if (BTRANS) {
        const int krow = (lane & 7) + ((lane >> 3) & 1) * 8;
        const int ncol8 = ((lane >> 4) & 1) * 8;
        #pragma unroll
        for (int p = 0; p < 4; p++)
            boff[p] = krow * ROWB_BT + (wn * 64 + p * 16 + ncol8) * 2;
    } else {
        const int brow = ((lane >> 4) << 3) + (lane & 7);
        const int kseg_b = (lane >> 3) & 1;
        #pragma unroll
        for (int p = 0; p < 4; p++)
            boff[p] = (wn * 64 + p * 16 + brow) * ROWB_BS + kseg_b * 16;
    }

    const int nc = K / BK;

    auto issue_loads = [&](int kc) {
        const uint32_t stu = sb + (kc & 1) * STAGE;
        const int kb = kc * BK;
        #pragma unroll
        for (int i = 0; i < 8; i++) {
            const int r = lr + i * 16;
            const long long g = zA + (long long)(m0 + r) * K + kb + lce;
            cp16(stu + r * ROWB_A + lcb, A_g + g);
        }
        if (BTRANS) {
            const int r0 = tid >> 5;
            const int cs = tid & 31;
            #pragma unroll
            for (int i = 0; i < 16; i++) {
                const int r = r0 + i * 8;
                const long long g = zB + (long long)(kb + r) * N + n0 + cs * 8;
                cp16(stu + OFF_B + r * ROWB_BT + cs * 16, B_g + g);
            }
        } else {
            #pragma unroll
            for (int i = 0; i < 16; i++) {
                const int r = lr + i * 16;
                const long long g = zB + (long long)(n0 + r) * K + kb + lce;
                cp16(stu + OFF_B + r * ROWB_BS + lcb, B_g + g);
            }
        }
    };

    // fragment loader for one ks step into buffer buf
    uint32_t ah[2][4][4], bb[2][4][2][2];
    auto load_frags = [&](uint32_t stu, int ks, int buf) {
        #pragma unroll
        for (int mt = 0; mt < 4; mt++)
            ldm_x4(stu + aoff[mt] + ks * 32,
                   ah[buf][mt][0], ah[buf][mt][1], ah[buf][mt][2], ah[buf][mt][3]);
        #pragma unroll
        for (int p = 0; p < 4; p++) {
            if (BTRANS)
                ldm_x4_t(stu + OFF_B + boff[p] + ks * 16 * ROWB_BT,
                         bb[buf][p][0][0], bb[buf][p][0][1], bb[buf][p][1][0], bb[buf][p][1][1]);
            else
                ldm_x4(stu + OFF_B + boff[p] + ks * 32,
                       bb[buf][p][0][0], bb[buf][p][0][1], bb[buf][p][1][0], bb[buf][p][1][1]);
        }
    };
    auto mma_block = [&](int buf) {
        #pragma unroll
        for (int p = 0; p < 4; p++)
            #pragma unroll
            for (int mt = 0; mt < 4; mt++) {
                mma16816(acc[mt][2 * p + 0], ah[buf][mt], bb[buf][p][0]);
                mma16816(acc[mt][2 * p + 1], ah[buf][mt], bb[buf][p][1]);
            }
    };

    // prologue: stage 0 in flight
    issue_loads(0); CP_COMMIT();

    for (int kc = 0; kc < nc; kc++) {
        CP_WAIT_ALL();        // exactly one group in flight: chunk kc
        __syncthreads();      // data visible + all warps done with stage kc-1
        if (kc + 1 < nc) { issue_loads(kc + 1); CP_COMMIT(); }

        const uint32_t stu = sb + (kc & 1) * STAGE;

        load_frags(stu, 0, 0);
        #pragma unroll
        for (int ks = 0; ks < 8; ks++) {
            if (ks < 7) load_frags(stu, ks + 1, (ks + 1) & 1);
            mma_block(ks & 1);
        }
    }

    // ---- epilogue ----
    const int gr = lane >> 2, qc = (lane & 3) * 2;
    #pragma unroll
    for (int mt = 0; mt < 4; mt++) {
        #pragma unroll
        for (int half_ = 0; half_ < 2; half_++) {
            const int m = m0 + wm * 64 + mt * 16 + gr + half_ * 8;
            const long long crow = zC + (long long)m * N;
            #pragma unroll
            for (int nt = 0; nt < 8; nt++) {
                const int c = n0 + wn * 64 + nt * 8 + qc;
                float v0 = acc[mt][nt][half_ * 2 + 0] * alpha;
                float v1 = acc[mt][nt][half_ * 2 + 1] * alpha;
                if (BIAS)  { v0 += __ldg(&bias[c]); v1 += __ldg(&bias[c + 1]); }
                if (RESID) { v0 += resid[crow + c]; v1 += resid[crow + c + 1]; }
                if (WF32)  { *(float2*)(Cf + crow + c) = make_float2(v0, v1); }
                if (WH) {
                    __half2 hv; hv.x = __float2half_rn(v0); hv.y = __float2half_rn(v1);
                    *(__half2*)(Ch + crow + c) = hv;
                }
            }
        }
    }
}

#define SMEM_STD (2 * (A_ARR + 256 * ROWB_BS))   // 208896
#define SMEM_TRN (2 * (A_ARR + BK * ROWB_BT))    // 204800

// ---------------------------------------------------------------------------
// GELU (exact erf) -> fp16, 8 elems/thread vectorized
// ---------------------------------------------------------------------------
__global__ __launch_bounds__(256)
void gelu_kernel(const float* __restrict__ in, __half* __restrict__ o, int n)
{
    int i = (blockIdx.x * blockDim.x + threadIdx.x) * 8;
    if (i < n) {
        float4 a = *(const float4*)(in + i);
        float4 b = *(const float4*)(in + i + 4);
        float r[8] = {a.x, a.y, a.z, a.w, b.x, b.y, b.z, b.w};
        __half h[8];
        #pragma unroll
        for (int j = 0; j < 8; j++) {
            float t = r[j];
            h[j] = __float2half_rn(0.5f * t * (1.0f + erff(t * 0.70710678118654752f)));
        }
        *(uint4*)(o + i) = *(uint4*)h;
    }
}

// ---------------------------------------------------------------------------
// Weight transpose:  W[K][N] fp32 -> Wt [N][K] fp16
// ---------------------------------------------------------------------------
__global__ __launch_bounds__(256)
void wt_kernel(const float* __restrict__ W, __half* __restrict__ T)
{
    __shared__ float t[32][33];
    const int n0 = blockIdx.x * 32, k0 = blockIdx.y * 32;
    const int tx = threadIdx.x, ty = threadIdx.y;
    #pragma unroll
    for (int i = 0; i < 4; i++)
        t[ty + i * 8][tx] = W[(k0 + ty + i * 8) * DM + n0 + tx];
    __syncthreads();
    #pragma unroll
    for (int i = 0; i < 4; i++)
        T[(n0 + ty + i * 8) * DM + k0 + tx] = __float2half_rn(t[tx][ty + i * 8]);
}

// ---------------------------------------------------------------------------
// Softmax over fp16 scores -> fp16 probs. 256 thr / row of 2048, uint4 I/O.
// ---------------------------------------------------------------------------
__global__ __launch_bounds__(256)
void softmax_kernel(const __half* __restrict__ S, __half* __restrict__ P)
{
    const long long row = (long long)blockIdx.x * SEQ;
    const int tid = threadIdx.x;
    __shared__ float red[8];

    uint4 pk = *(const uint4*)(S + row + tid * 8);
    __half h[8];
    *(uint4*)h = pk;
    float v[8];
    #pragma unroll
    for (int i = 0; i < 8; i++) v[i] = __half2float(h[i]);

    float mx = v[0];
    #pragma unroll
    for (int i = 1; i < 8; i++) mx = fmaxf(mx, v[i]);
    #pragma unroll
    for (int o = 16; o > 0; o >>= 1) mx = fmaxf(mx, __shfl_xor_sync(0xffffffffu, mx, o));
    if ((tid & 31) == 0) red[tid >> 5] = mx;
    __syncthreads();
    float rmax = red[0];
    #pragma unroll
    for (int i = 1; i < 8; i++) rmax = fmaxf(rmax, red[i]);
    __syncthreads();

    float sum = 0.0f;
    #pragma unroll
    for (int i = 0; i < 8; i++) { v[i] = __expf(v[i] - rmax); sum += v[i]; }
    #pragma unroll
    for (int o = 16; o > 0; o >>= 1) sum += __shfl_xor_sync(0xffffffffu, sum, o);
    if ((tid & 31) == 0) red[tid >> 5] = sum;
    __syncthreads();
    float rsum = 0.0f;
    #pragma unroll
    for (int i = 0; i < 8; i++) rsum += red[i];
    const float inv = 1.0f / rsum;

    #pragma unroll
    for (int i = 0; i < 8; i++) h[i] = __float2half_rn(v[i] * inv);
    *(uint4*)(P + row + tid * 8) = *(uint4*)h;
}

// ---------------------------------------------------------------------------
// Launch
// ---------------------------------------------------------------------------
extern "C" void kernel_launch(void* const* d_in, const int* in_sizes, int n_in,
                              void* d_out, int out_size)
{
    const float* tokens = (const float*)d_in[0];
    const float* Wq = (const float*)d_in[1];
    const float* bq = (const float*)d_in[2];
    const float* Wk = (const float*)d_in[3];
    const float* bk = (const float*)d_in[4];
    const float* Wv = (const float*)d_in[5];
    const float* bv = (const float*)d_in[6];
    const float* Wo = (const float*)d_in[7];
    const float* bo = (const float*)d_in[8];
    float* out = (float*)d_out;

    __half *x, *wt, *q, *k, *v, *s, *pp, *m;
    cudaGetSymbolAddress((void**)&x, g_x);
    cudaGetSymbolAddress((void**)&wt, g_wt);
    cudaGetSymbolAddress((void**)&q, g_q);
    cudaGetSymbolAddress((void**)&k, g_k);
    cudaGetSymbolAddress((void**)&v, g_v);
    cudaGetSymbolAddress((void**)&s, g_s);
    cudaGetSymbolAddress((void**)&pp, g_p);
    cudaGetSymbolAddress((void**)&m, g_m);

    // raise smem cap on every launched instantiation
    cudaFuncSetAttribute(gemm_mma<true,  false, false, true,  false>, cudaFuncAttributeMaxDynamicSharedMemorySize, SMEM_STD);
    cudaFuncSetAttribute(gemm_mma<false, false, false, true,  false>, cudaFuncAttributeMaxDynamicSharedMemorySize, SMEM_STD);
    cudaFuncSetAttribute(gemm_mma<false, false, false, true,  true >, cudaFuncAttributeMaxDynamicSharedMemorySize, SMEM_TRN);
    cudaFuncSetAttribute(gemm_mma<true,  true,  true,  false, false>, cudaFuncAttributeMaxDynamicSharedMemorySize, SMEM_STD);

    const int nTok = BS * DM;
    const float scale = 1.0f / 32.0f;

    // 1) gelu -> fp16 (vectorized, 8/thread)
    gelu_kernel<<<nTok / 8 / 256, 256>>>(tokens, x, nTok);

    // 2) weight transposes -> fp16
    {
        dim3 grid(32, 32), blk(32, 8);
        wt_kernel<<<grid, blk>>>(Wq, wt + 0 * DM * DM);
        wt_kernel<<<grid, blk>>>(Wk, wt + 1 * DM * DM);
        wt_kernel<<<grid, blk>>>(Wv, wt + 2 * DM * DM);
        wt_kernel<<<grid, blk>>>(Wo, wt + 3 * DM * DM);
    }

    // 3) Q, K, V projections -> fp16
    {
        dim3 grid(DM / BN, BS / BM, 1);
        gemm_mma<true, false, false, true, false><<<grid, 256, SMEM_STD>>>(
            x, wt + 0 * DM * DM, bq, nullptr, nullptr, q, BS, DM, DM, 1.0f, 0, 0, 0);
        gemm_mma<true, false, false, true, false><<<grid, 256, SMEM_STD>>>(
            x, wt + 1 * DM * DM, bk, nullptr, nullptr, k, BS, DM, DM, 1.0f, 0, 0, 0);
        gemm_mma<true, false, false, true, false><<<grid, 256, SMEM_STD>>>(
            x, wt + 2 * DM * DM, bv, nullptr, nullptr, v, BS, DM, DM, 1.0f, 0, 0, 0);
    }

    // 4) scores = scale * Q @ K^T (batched) -> fp16
    {
        dim3 grid(SEQ / BN, SEQ / BM, BATCH);
        gemm_mma<false, false, false, true, false><<<grid, 256, SMEM_STD>>>(
            q, k, nullptr, nullptr, nullptr, s, SEQ, SEQ, DM, scale,
            (long long)SEQ * DM, (long long)SEQ * DM, (long long)SEQ * SEQ);
    }

    // 5) softmax -> fp16 probs
    softmax_kernel<<<BS, 256>>>(s, pp);

    // 6) mixed = attn @ V (batched, V natural layout via trans-ldmatrix) -> fp16
    {
        dim3 grid(DM / BN, SEQ / BM, BATCH);
        gemm_mma<false, false, false, true, true><<<grid, 256, SMEM_TRN>>>(
            pp, v, nullptr, nullptr, nullptr, m, SEQ, DM, SEQ, 1.0f,
            (long long)SEQ * SEQ, (long long)SEQ * DM, (long long)SEQ * DM);
    }

    // 7) out = mixed @ Wo^T + bo + tokens -> fp32
    {
        dim3 grid(DM / BN, BS / BM, 1);
        gemm_mma<true, true, true, false, false><<<grid, 256, SMEM_STD>>>(
            m, wt + 3 * DM * DM, bo, tokens, out, nullptr, BS, DM, DM, 1.0f, 0, 0, 0);
    }
}